// round 1
// baseline (speedup 1.0000x reference)
#include <cuda_runtime.h>
#include <math.h>

// ---------------- constants ----------------
#define DMODEL 768
#define NHEAD  12
#define DHEAD  64
#define NLAYER 4
#define PPF    256
#define SDIM   2048   // TF * PPF
#define TFRM   8
#define EXPD   3072   // EXP * D
#define MODW   4608   // 6*D
#define EPSV   1e-6f

// ---------------- scratch (module-load allocated, not counted as runtime alloc) ----------------
__device__ float g_tokens[SDIM*DMODEL];
__device__ float g_cond[TFRM*DMODEL];
__device__ float g_mod[TFRM*MODW];
__device__ float g_h[SDIM*DMODEL];
__device__ float g_qkv[SDIM*3*DMODEL];
__device__ float g_qn[NHEAD*SDIM*DHEAD];
__device__ float g_kn[NHEAD*SDIM*DHEAD];
__device__ float g_vv[NHEAD*SDIM*DHEAD];
__device__ float g_z[SDIM*DMODEL];
__device__ float g_u[SDIM*EXPD];
__device__ float g_act[SDIM*EXPD];
__device__ float g_mf[TFRM*2*DMODEL];

// ---------------- patchify: conv k5 s4 p2 + pos-embed ----------------
__global__ void patchify_kernel(const float* __restrict__ x, const float* __restrict__ cw,
                                const float* __restrict__ cb, const float* __restrict__ pe) {
    int s = blockIdx.x;
    int t = s >> 8, p = s & 255, oy = p >> 4, ox = p & 15;
    __shared__ float patch[75];
    int tid = threadIdx.x;
    if (tid < 75) {
        int c = tid / 25, rem = tid % 25, r = rem / 5, w = rem % 5;
        int iy = oy*4 - 2 + r, ix = ox*4 - 2 + w;
        float v = 0.f;
        if (iy >= 0 && iy < 64 && ix >= 0 && ix < 64)
            v = x[((t*3 + c)*64 + iy)*64 + ix];
        patch[tid] = v;
    }
    __syncthreads();
    for (int d = tid; d < DMODEL; d += 256) {
        float acc = cb[d];
        const float* w = cw + d*75;
        #pragma unroll
        for (int i = 0; i < 75; i++) acc += patch[i] * w[i];
        g_tokens[s*DMODEL + d] = acc + pe[p*DMODEL + d];
    }
}

// ---------------- conditioning: silu(te[ts_int] + ae[action]) ----------------
__global__ void cond_kernel(const int* __restrict__ actions, const float* __restrict__ ts,
                            const float* __restrict__ ae) {
    int f = blockIdx.x;
    int a = actions[f];
    float tsv = ts[f];
    int ti = (int)(tsv * 1000.0f);
    if (ti > 999) ti = 999;
    float tif = (float)ti;
    for (int d = threadIdx.x; d < DMODEL; d += blockDim.x) {
        int j = (d < 384) ? d : d - 384;
        float th = powf(500.0f, -((float)j) / 384.0f);
        float ang = tif * th;
        float te = (d < 384) ? sinf(ang) : cosf(ang);
        float c = te + ae[a*DMODEL + d];
        g_cond[f*DMODEL + d] = c / (1.f + expf(-c));
    }
}

// ---------------- small-M GEMM: C[8,N] = A[8,768] @ B[768,N] + bias ----------------
__global__ void smallm_gemm(const float* __restrict__ A, const float* __restrict__ B,
                            const float* __restrict__ bias, float* __restrict__ C, int N) {
    __shared__ float As[8*DMODEL];
    int tid = threadIdx.x;
    for (int i = tid; i < 8*DMODEL; i += 256) As[i] = A[i];
    __syncthreads();
    int col = tid & 127, rg = tid >> 7;
    int n = blockIdx.x * 128 + col;
    float acc0 = 0, acc1 = 0, acc2 = 0, acc3 = 0;
    int rb = rg * 4;
    for (int k = 0; k < DMODEL; k++) {
        float bv = B[(size_t)k * N + n];
        acc0 += As[(rb+0)*DMODEL + k] * bv;
        acc1 += As[(rb+1)*DMODEL + k] * bv;
        acc2 += As[(rb+2)*DMODEL + k] * bv;
        acc3 += As[(rb+3)*DMODEL + k] * bv;
    }
    float bs = bias[n];
    C[(rb+0)*N + n] = acc0 + bs;
    C[(rb+1)*N + n] = acc1 + bs;
    C[(rb+2)*N + n] = acc2 + bs;
    C[(rb+3)*N + n] = acc3 + bs;
}

// ---------------- RMSNorm + AdaLN modulate ----------------
__global__ void modulate_kernel(const float* __restrict__ in, float* __restrict__ out,
                                const float* __restrict__ sa, const float* __restrict__ mod,
                                int mstride, int off_sc, int off_b) {
    int s = blockIdx.x, tid = threadIdx.x, f = s >> 8;
    const float* row = in + (size_t)s * DMODEL;
    float v0 = row[tid], v1 = row[tid+256], v2 = row[tid+512];
    float ss = v0*v0 + v1*v1 + v2*v2;
    __shared__ float red[8];
    #pragma unroll
    for (int o = 16; o > 0; o >>= 1) ss += __shfl_xor_sync(0xffffffffu, ss, o);
    if ((tid & 31) == 0) red[tid >> 5] = ss;
    __syncthreads();
    float tot = 0.f;
    #pragma unroll
    for (int w = 0; w < 8; w++) tot += red[w];
    float rinv = 1.f / (sqrtf(tot * (1.f/768.f)) + EPSV);
    const float* mrow = mod + f * mstride;
    float* orow = out + (size_t)s * DMODEL;
    int d = tid;
    orow[d] = v0 * rinv * sa[d] * (1.f + mrow[off_sc + d]) + mrow[off_b + d];
    d = tid + 256;
    orow[d] = v1 * rinv * sa[d] * (1.f + mrow[off_sc + d]) + mrow[off_b + d];
    d = tid + 512;
    orow[d] = v2 * rinv * sa[d] * (1.f + mrow[off_sc + d]) + mrow[off_b + d];
}

// ---------------- main GEMM: 128x128x8 tiles, 8x8 micro ----------------
// EPI 0: C = acc
// EPI 1: C += acc * gate[frame(m)*4608 + n]   (residual gate; aux pre-offset)
// EPI 2: C = aux[m*N+n] * silu(acc)           (gated MLP; aux = u buffer)
template<int EPI>
__global__ void __launch_bounds__(256) gemm128(const float* __restrict__ A,
                                               const float* __restrict__ B,
                                               float* __restrict__ C,
                                               int M, int N, int K,
                                               const float* __restrict__ aux) {
    __shared__ float As[8][128];
    __shared__ float Bs[8][128];
    int tid = threadIdx.x;
    int m0 = blockIdx.y * 128, n0 = blockIdx.x * 128;
    int tx = tid & 15, ty = tid >> 4;
    int r0 = ty * 8, c0 = tx * 8;
    float acc[8][8];
    #pragma unroll
    for (int i = 0; i < 8; i++)
        #pragma unroll
        for (int j = 0; j < 8; j++) acc[i][j] = 0.f;

    int am = tid >> 1, ak = (tid & 1) * 4;
    int bk = tid >> 5, bn = (tid & 31) * 4;
    const float* Aptr = A + (size_t)(m0 + am) * K + ak;
    const float* Bptr = B + (size_t)bk * N + n0 + bn;

    for (int k0 = 0; k0 < K; k0 += 8) {
        float4 va = *(const float4*)(Aptr + k0);
        float4 vb = *(const float4*)(Bptr + (size_t)k0 * N);
        __syncthreads();
        As[ak+0][am] = va.x; As[ak+1][am] = va.y;
        As[ak+2][am] = va.z; As[ak+3][am] = va.w;
        *(float4*)&Bs[bk][bn] = vb;
        __syncthreads();
        #pragma unroll
        for (int k = 0; k < 8; k++) {
            float4 a0 = *(float4*)&As[k][r0];
            float4 a1 = *(float4*)&As[k][r0+4];
            float4 b0 = *(float4*)&Bs[k][c0];
            float4 b1 = *(float4*)&Bs[k][c0+4];
            float a[8] = {a0.x,a0.y,a0.z,a0.w,a1.x,a1.y,a1.z,a1.w};
            float b[8] = {b0.x,b0.y,b0.z,b0.w,b1.x,b1.y,b1.z,b1.w};
            #pragma unroll
            for (int i = 0; i < 8; i++)
                #pragma unroll
                for (int j = 0; j < 8; j++) acc[i][j] += a[i] * b[j];
        }
    }
    #pragma unroll
    for (int ii = 0; ii < 8; ii++) {
        int m = m0 + r0 + ii;
        float* crow = C + (size_t)m * N + n0 + c0;
        if (EPI == 0) {
            #pragma unroll
            for (int jj = 0; jj < 8; jj++) crow[jj] = acc[ii][jj];
        } else if (EPI == 1) {
            const float* g = aux + (size_t)(m >> 8) * MODW + n0 + c0;
            #pragma unroll
            for (int jj = 0; jj < 8; jj++) crow[jj] += acc[ii][jj] * g[jj];
        } else {
            const float* u = aux + (size_t)m * N + n0 + c0;
            #pragma unroll
            for (int jj = 0; jj < 8; jj++) {
                float gv = acc[ii][jj];
                crow[jj] = u[jj] * (gv / (1.f + expf(-gv)));
            }
        }
    }
}

// ---------------- qkv split + per-head RMSNorm ----------------
__global__ void splitnorm_kernel(const float* __restrict__ sq, const float* __restrict__ sk) {
    int s = blockIdx.x, hh = blockIdx.y, d = threadIdx.x;
    const float* base = g_qkv + (size_t)s * (3*DMODEL) + hh * DHEAD;
    float qv = base[d], kv = base[DMODEL + d], vv = base[2*DMODEL + d];
    __shared__ float red[4];
    float qs = qv * qv, ks = kv * kv;
    #pragma unroll
    for (int o = 16; o > 0; o >>= 1) {
        qs += __shfl_xor_sync(0xffffffffu, qs, o);
        ks += __shfl_xor_sync(0xffffffffu, ks, o);
    }
    if ((d & 31) == 0) { red[d >> 5] = qs; red[2 + (d >> 5)] = ks; }
    __syncthreads();
    float qr = 1.f / (sqrtf((red[0]+red[1]) * (1.f/64.f)) + EPSV);
    float kr = 1.f / (sqrtf((red[2]+red[3]) * (1.f/64.f)) + EPSV);
    size_t o = ((size_t)hh * SDIM + s) * DHEAD + d;
    g_qn[o] = qv * qr * sq[d];
    g_kn[o] = kv * kr * sk[d];
    g_vv[o] = vv;
}

// ---------------- flash attention (block-causal by frame, unscaled logits) ----------------
__global__ void __launch_bounds__(256) flash_kernel() {
    extern __shared__ float sm[];
    float* Qs = sm;            // [64][65] d-major: Qs[d*65+i]
    float* Ks = sm + 4160;     // Ks[d*65+j]
    float* Vs = sm + 8320;     // Vs[j*65+dc]
    float* Ps = sm + 12480;    // Ps[j*65+i]
    int qb = blockIdx.x, hh = blockIdx.y;
    int q0 = qb * 64;
    int nk = ((qb >> 2) + 1) * 4;
    int tid = threadIdx.x, tx = tid & 15, ty = tid >> 4;
    int ri = ty * 4, cj = tx * 4;

    const float* qbase = g_qn + ((size_t)hh * SDIM + q0) * DHEAD;
    for (int idx = tid; idx < 4096; idx += 256) {
        int i = idx >> 6, d = idx & 63;
        Qs[d*65 + i] = qbase[idx];  // qbase[i*64+d] == qbase[idx]
    }
    float mm[4], ll[4], ov[4][4];
    #pragma unroll
    for (int i = 0; i < 4; i++) {
        mm[i] = -1e30f; ll[i] = 0.f;
        #pragma unroll
        for (int j = 0; j < 4; j++) ov[i][j] = 0.f;
    }

    for (int kt = 0; kt < nk; kt++) {
        const float* kbase = g_kn + ((size_t)hh * SDIM + kt*64) * DHEAD;
        const float* vbase = g_vv + ((size_t)hh * SDIM + kt*64) * DHEAD;
        __syncthreads();
        for (int idx = tid; idx < 4096; idx += 256) {
            int j = idx >> 6, d = idx & 63;
            Ks[d*65 + j] = kbase[idx];
            Vs[j*65 + d] = vbase[idx];
        }
        __syncthreads();

        float sc[4][4];
        #pragma unroll
        for (int i = 0; i < 4; i++)
            #pragma unroll
            for (int j = 0; j < 4; j++) sc[i][j] = 0.f;
        #pragma unroll 4
        for (int d = 0; d < 64; d++) {
            float a[4], b[4];
            #pragma unroll
            for (int i = 0; i < 4; i++) a[i] = Qs[d*65 + ri + i];
            #pragma unroll
            for (int j = 0; j < 4; j++) b[j] = Ks[d*65 + cj + j];
            #pragma unroll
            for (int i = 0; i < 4; i++)
                #pragma unroll
                for (int j = 0; j < 4; j++) sc[i][j] += a[i] * b[j];
        }
        // online softmax (rows owned by the 16 tx-lanes within half-warp)
        #pragma unroll
        for (int i = 0; i < 4; i++) {
            float mx = fmaxf(fmaxf(sc[i][0], sc[i][1]), fmaxf(sc[i][2], sc[i][3]));
            #pragma unroll
            for (int o = 1; o < 16; o <<= 1) mx = fmaxf(mx, __shfl_xor_sync(0xffffffffu, mx, o));
            float mn = fmaxf(mm[i], mx);
            float scale = expf(mm[i] - mn);
            float rs = 0.f;
            #pragma unroll
            for (int j = 0; j < 4; j++) {
                float p = expf(sc[i][j] - mn);
                sc[i][j] = p; rs += p;
            }
            #pragma unroll
            for (int o = 1; o < 16; o <<= 1) rs += __shfl_xor_sync(0xffffffffu, rs, o);
            ll[i] = ll[i] * scale + rs;
            mm[i] = mn;
            #pragma unroll
            for (int j = 0; j < 4; j++) ov[i][j] *= scale;
        }
        #pragma unroll
        for (int i = 0; i < 4; i++)
            #pragma unroll
            for (int j = 0; j < 4; j++)
                Ps[(cj + j)*65 + ri + i] = sc[i][j];
        __syncthreads();
        #pragma unroll 4
        for (int j = 0; j < 64; j++) {
            float a[4], b[4];
            #pragma unroll
            for (int i = 0; i < 4; i++) a[i] = Ps[j*65 + ri + i];
            #pragma unroll
            for (int jc = 0; jc < 4; jc++) b[jc] = Vs[j*65 + cj + jc];
            #pragma unroll
            for (int i = 0; i < 4; i++)
                #pragma unroll
                for (int jc = 0; jc < 4; jc++) ov[i][jc] += a[i] * b[jc];
        }
    }
    #pragma unroll
    for (int i = 0; i < 4; i++) {
        float inv = 1.f / ll[i];
        int row = q0 + ri + i;
        #pragma unroll
        for (int j = 0; j < 4; j++)
            g_z[(size_t)row * DMODEL + hh*DHEAD + cj + j] = ov[i][j] * inv;
    }
}

// ---------------- output projection + unpatchify ----------------
__global__ void outproj_kernel(const float* __restrict__ Wout, const float* __restrict__ bout,
                               float* __restrict__ out) {
    __shared__ float row[DMODEL];
    int s = blockIdx.x, tid = threadIdx.x;
    for (int i = tid; i < DMODEL; i += 64) row[i] = g_h[(size_t)s * DMODEL + i];
    __syncthreads();
    if (tid < 48) {
        float acc = bout[tid];
        for (int k = 0; k < DMODEL; k++) acc += row[k] * Wout[k*48 + tid];
        int t = s >> 8, p = s & 255, oy = p >> 4, ox = p & 15;
        int c = tid >> 4, pi = (tid >> 2) & 3, pj = tid & 3;
        out[((t*3 + c)*64 + oy*4 + pi)*64 + ox*4 + pj] = acc;
    }
}

// ---------------- host ----------------
extern "C" void kernel_launch(void* const* d_in, const int* in_sizes, int n_in,
                              void* d_out, int out_size) {
    const float* x      = (const float*)d_in[0];
    const int*   actions= (const int*)  d_in[1];
    const float* ts     = (const float*)d_in[2];
    const float* conv_w = (const float*)d_in[3];
    const float* conv_b = (const float*)d_in[4];
    const float* pe     = (const float*)d_in[5];
    const float* ae     = (const float*)d_in[6];
    const float* Wmod   = (const float*)d_in[7];
    const float* bmod   = (const float*)d_in[8];
    const float* s1     = (const float*)d_in[9];
    const float* Wqkv   = (const float*)d_in[10];
    const float* Wo     = (const float*)d_in[11];
    const float* sq     = (const float*)d_in[12];
    const float* sk     = (const float*)d_in[13];
    const float* s2     = (const float*)d_in[14];
    const float* Wup    = (const float*)d_in[15];
    const float* Wgate  = (const float*)d_in[16];
    const float* Wdown  = (const float*)d_in[17];
    const float* s_final= (const float*)d_in[18];
    const float* Wmf    = (const float*)d_in[19];
    const float* bmf    = (const float*)d_in[20];
    const float* Wout   = (const float*)d_in[21];
    const float* bout   = (const float*)d_in[22];
    float* out = (float*)d_out;

    float *p_tokens, *p_cond, *p_mod, *p_h, *p_qkv, *p_z, *p_u, *p_act, *p_mf;
    cudaGetSymbolAddress((void**)&p_tokens, g_tokens);
    cudaGetSymbolAddress((void**)&p_cond,   g_cond);
    cudaGetSymbolAddress((void**)&p_mod,    g_mod);
    cudaGetSymbolAddress((void**)&p_h,      g_h);
    cudaGetSymbolAddress((void**)&p_qkv,    g_qkv);
    cudaGetSymbolAddress((void**)&p_z,      g_z);
    cudaGetSymbolAddress((void**)&p_u,      g_u);
    cudaGetSymbolAddress((void**)&p_act,    g_act);
    cudaGetSymbolAddress((void**)&p_mf,     g_mf);

    cudaFuncSetAttribute(flash_kernel, cudaFuncAttributeMaxDynamicSharedMemorySize, 66560);

    patchify_kernel<<<SDIM, 256>>>(x, conv_w, conv_b, pe);
    cond_kernel<<<TFRM, 256>>>(actions, ts, ae);

    for (int l = 0; l < NLAYER; l++) {
        const float* Wm  = Wmod  + (size_t)l * DMODEL * MODW;
        const float* bm  = bmod  + (size_t)l * MODW;
        const float* s1l = s1    + (size_t)l * DMODEL;
        const float* Wq  = Wqkv  + (size_t)l * DMODEL * 3*DMODEL;
        const float* Wol = Wo    + (size_t)l * DMODEL * DMODEL;
        const float* sql = sq    + (size_t)l * DHEAD;
        const float* skl = sk    + (size_t)l * DHEAD;
        const float* s2l = s2    + (size_t)l * DMODEL;
        const float* Wul = Wup   + (size_t)l * DMODEL * EXPD;
        const float* Wgl = Wgate + (size_t)l * DMODEL * EXPD;
        const float* Wdl = Wdown + (size_t)l * EXPD * DMODEL;

        smallm_gemm<<<MODW/128, 256>>>(p_cond, Wm, bm, p_mod, MODW);
        modulate_kernel<<<SDIM, 256>>>(p_tokens, p_h, s1l, p_mod, MODW, 0, 768);
        gemm128<0><<<dim3(3*DMODEL/128, SDIM/128), 256>>>(p_h, Wq, p_qkv, SDIM, 3*DMODEL, DMODEL, nullptr);
        splitnorm_kernel<<<dim3(SDIM, NHEAD), 64>>>(sql, skl);
        flash_kernel<<<dim3(SDIM/64, NHEAD), 256, 66560>>>();
        gemm128<1><<<dim3(DMODEL/128, SDIM/128), 256>>>(p_z, Wol, p_tokens, SDIM, DMODEL, DMODEL, p_mod + 1536);
        modulate_kernel<<<SDIM, 256>>>(p_tokens, p_h, s2l, p_mod, MODW, 2304, 3072);
        gemm128<0><<<dim3(EXPD/128, SDIM/128), 256>>>(p_h, Wul, p_u, SDIM, EXPD, DMODEL, nullptr);
        gemm128<2><<<dim3(EXPD/128, SDIM/128), 256>>>(p_h, Wgl, p_act, SDIM, EXPD, DMODEL, p_u);
        gemm128<1><<<dim3(DMODEL/128, SDIM/128), 256>>>(p_act, Wdl, p_tokens, SDIM, DMODEL, EXPD, p_mod + 3840);
    }

    smallm_gemm<<<2*DMODEL/128, 256>>>(p_cond, Wmf, bmf, p_mf, 2*DMODEL);
    modulate_kernel<<<SDIM, 256>>>(p_tokens, p_h, s_final, p_mf, 2*DMODEL, 0, 768);
    outproj_kernel<<<SDIM, 64>>>(Wout, bout, out);
}

// round 3
// speedup vs baseline: 1.1495x; 1.1495x over previous
#include <cuda_runtime.h>
#include <math.h>
#include <stdint.h>

// ---------------- constants ----------------
#define DMODEL 768
#define NHEAD  12
#define DHEAD  64
#define NLAYER 4
#define PPF    256
#define SDIM   2048   // TF * PPF
#define TFRM   8
#define EXPD   3072   // EXP * D
#define MODW   4608   // 6*D
#define EPSV   1e-6f

// ---------------- scratch ----------------
__device__ float g_tokens[SDIM*DMODEL];
__device__ float g_cond[TFRM*DMODEL];
__device__ float g_mod[TFRM*MODW];
__device__ float g_h[SDIM*DMODEL];
__device__ float g_qkv[SDIM*3*DMODEL];
__device__ float g_qn[NHEAD*SDIM*DHEAD];
__device__ float g_kn[NHEAD*SDIM*DHEAD];
__device__ float g_vv[NHEAD*SDIM*DHEAD];
__device__ float g_z[SDIM*DMODEL];
__device__ float g_u[SDIM*EXPD];
__device__ float g_act[SDIM*EXPD];
__device__ float g_mf[TFRM*2*DMODEL];

__device__ __forceinline__ float tf32r(float v) {
    uint32_t o;
    asm("cvt.rna.tf32.f32 %0, %1;" : "=r"(o) : "f"(v));
    return __uint_as_float(o);
}

// ---------------- patchify: conv k5 s4 p2 + pos-embed ----------------
__global__ void patchify_kernel(const float* __restrict__ x, const float* __restrict__ cw,
                                const float* __restrict__ cb, const float* __restrict__ pe) {
    int s = blockIdx.x;
    int t = s >> 8, p = s & 255, oy = p >> 4, ox = p & 15;
    __shared__ float patch[75];
    int tid = threadIdx.x;
    if (tid < 75) {
        int c = tid / 25, rem = tid % 25, r = rem / 5, w = rem % 5;
        int iy = oy*4 - 2 + r, ix = ox*4 - 2 + w;
        float v = 0.f;
        if (iy >= 0 && iy < 64 && ix >= 0 && ix < 64)
            v = x[((t*3 + c)*64 + iy)*64 + ix];
        patch[tid] = v;
    }
    __syncthreads();
    for (int d = tid; d < DMODEL; d += 256) {
        float acc = cb[d];
        const float* w = cw + d*75;
        #pragma unroll
        for (int i = 0; i < 75; i++) acc += patch[i] * w[i];
        g_tokens[s*DMODEL + d] = acc + pe[p*DMODEL + d];
    }
}

// ---------------- conditioning ----------------
__global__ void cond_kernel(const int* __restrict__ actions, const float* __restrict__ ts,
                            const float* __restrict__ ae) {
    int f = blockIdx.x;
    int a = actions[f];
    float tsv = ts[f];
    int ti = (int)(tsv * 1000.0f);
    if (ti > 999) ti = 999;
    float tif = (float)ti;
    for (int d = threadIdx.x; d < DMODEL; d += blockDim.x) {
        int j = (d < 384) ? d : d - 384;
        float th = powf(500.0f, -((float)j) / 384.0f);
        float ang = tif * th;
        float te = (d < 384) ? sinf(ang) : cosf(ang);
        float c = te + ae[a*DMODEL + d];
        g_cond[f*DMODEL + d] = c / (1.f + expf(-c));
    }
}

// ---------------- small-M GEMM: C[8,N] = A[8,768] @ B[768,N] + bias ----------------
__global__ void smallm_gemm(const float* __restrict__ A, const float* __restrict__ B,
                            const float* __restrict__ bias, float* __restrict__ C, int N) {
    __shared__ float As[8*DMODEL];
    int tid = threadIdx.x;
    for (int i = tid; i < 8*DMODEL; i += 256) As[i] = A[i];
    __syncthreads();
    int col = tid & 127, rg = tid >> 7;
    int n = blockIdx.x * 128 + col;
    float acc0 = 0, acc1 = 0, acc2 = 0, acc3 = 0;
    int rb = rg * 4;
    for (int k = 0; k < DMODEL; k++) {
        float bv = B[(size_t)k * N + n];
        acc0 += As[(rb+0)*DMODEL + k] * bv;
        acc1 += As[(rb+1)*DMODEL + k] * bv;
        acc2 += As[(rb+2)*DMODEL + k] * bv;
        acc3 += As[(rb+3)*DMODEL + k] * bv;
    }
    float bs = bias[n];
    C[(rb+0)*N + n] = acc0 + bs;
    C[(rb+1)*N + n] = acc1 + bs;
    C[(rb+2)*N + n] = acc2 + bs;
    C[(rb+3)*N + n] = acc3 + bs;
}

// ---------------- RMSNorm + AdaLN modulate ----------------
__global__ void modulate_kernel(const float* __restrict__ in, float* __restrict__ out,
                                const float* __restrict__ sa, const float* __restrict__ mod,
                                int mstride, int off_sc, int off_b) {
    int s = blockIdx.x, tid = threadIdx.x, f = s >> 8;
    const float* row = in + (size_t)s * DMODEL;
    float v0 = row[tid], v1 = row[tid+256], v2 = row[tid+512];
    float ss = v0*v0 + v1*v1 + v2*v2;
    __shared__ float red[8];
    #pragma unroll
    for (int o = 16; o > 0; o >>= 1) ss += __shfl_xor_sync(0xffffffffu, ss, o);
    if ((tid & 31) == 0) red[tid >> 5] = ss;
    __syncthreads();
    float tot = 0.f;
    #pragma unroll
    for (int w = 0; w < 8; w++) tot += red[w];
    float rinv = 1.f / (sqrtf(tot * (1.f/768.f)) + EPSV);
    const float* mrow = mod + f * mstride;
    float* orow = out + (size_t)s * DMODEL;
    int d = tid;
    orow[d] = v0 * rinv * sa[d] * (1.f + mrow[off_sc + d]) + mrow[off_b + d];
    d = tid + 256;
    orow[d] = v1 * rinv * sa[d] * (1.f + mrow[off_sc + d]) + mrow[off_b + d];
    d = tid + 512;
    orow[d] = v2 * rinv * sa[d] * (1.f + mrow[off_sc + d]) + mrow[off_b + d];
}

// ---------------- 3xTF32 tensor-core GEMM: 128x128x16 tiles, mma.m16n8k8 ----------------
// Both operands split hi/lo; acc += ah*bh + al*bh + ah*bl  (al*bl dropped, ~2^-22)
// EPI 0: C = acc
// EPI 1: C += acc * gate[frame(m)*MODW + n]
// EPI 2: C = aux[m*N+n] * silu(acc)
#define SA 20    // As[128][20] m-major
#define SB 136   // Bs[16][136] k-major

template<int EPI>
__global__ void __launch_bounds__(256) gemm_tc(const float* __restrict__ A,
                                               const float* __restrict__ B,
                                               float* __restrict__ C,
                                               int M, int N, int K,
                                               const float* __restrict__ aux) {
    __shared__ float Ah[128][SA];
    __shared__ float Al[128][SA];
    __shared__ float Bh[16][SB];
    __shared__ float Bl[16][SB];
    int tid = threadIdx.x;
    int m0 = blockIdx.y * 128, n0 = blockIdx.x * 128;
    int lane = tid & 31, wid = tid >> 5;
    int wm = wid >> 2, wn = wid & 3;          // warp tile: 64m x 32n
    int g = lane >> 2, tg = lane & 3;

    float acc[4][4][4];
    #pragma unroll
    for (int i = 0; i < 4; i++)
        #pragma unroll
        for (int j = 0; j < 4; j++)
            #pragma unroll
            for (int c = 0; c < 4; c++) acc[i][j][c] = 0.f;

    const float* Ag = A + (size_t)m0 * K;
    const float* Bg = B + n0;

    int a_m[2], a_kq[2], b_k[2], b_n[2];
    #pragma unroll
    for (int t = 0; t < 2; t++) {
        int idx = tid + t*256;
        a_m[t] = idx >> 2; a_kq[t] = idx & 3;
        b_k[t] = idx >> 5; b_n[t] = (idx & 31) * 4;
    }

    for (int k0 = 0; k0 < K; k0 += 16) {
        float4 av[2], bv[2];
        #pragma unroll
        for (int t = 0; t < 2; t++) {
            av[t] = *(const float4*)(Ag + (size_t)a_m[t] * K + k0 + a_kq[t]*4);
            bv[t] = *(const float4*)(Bg + (size_t)(k0 + b_k[t]) * N + b_n[t]);
        }
        __syncthreads();
        #pragma unroll
        for (int t = 0; t < 2; t++) {
            float* aph = &Ah[a_m[t]][a_kq[t]*4];
            float* apl = &Al[a_m[t]][a_kq[t]*4];
            float h;
            h = tf32r(av[t].x); aph[0] = h; apl[0] = tf32r(av[t].x - h);
            h = tf32r(av[t].y); aph[1] = h; apl[1] = tf32r(av[t].y - h);
            h = tf32r(av[t].z); aph[2] = h; apl[2] = tf32r(av[t].z - h);
            h = tf32r(av[t].w); aph[3] = h; apl[3] = tf32r(av[t].w - h);
            float* bph = &Bh[b_k[t]][b_n[t]];
            float* bpl = &Bl[b_k[t]][b_n[t]];
            h = tf32r(bv[t].x); bph[0] = h; bpl[0] = tf32r(bv[t].x - h);
            h = tf32r(bv[t].y); bph[1] = h; bpl[1] = tf32r(bv[t].y - h);
            h = tf32r(bv[t].z); bph[2] = h; bpl[2] = tf32r(bv[t].z - h);
            h = tf32r(bv[t].w); bph[3] = h; bpl[3] = tf32r(bv[t].w - h);
        }
        __syncthreads();
        #pragma unroll
        for (int k8 = 0; k8 < 2; k8++) {
            int kb = k8 * 8;
            uint32_t ah[4][4], al[4][4], bh[4][2], bl[4][2];
            #pragma unroll
            for (int i = 0; i < 4; i++) {
                int m = wm*64 + i*16 + g;
                ah[i][0] = __float_as_uint(Ah[m  ][kb + tg]);
                ah[i][1] = __float_as_uint(Ah[m+8][kb + tg]);
                ah[i][2] = __float_as_uint(Ah[m  ][kb + tg + 4]);
                ah[i][3] = __float_as_uint(Ah[m+8][kb + tg + 4]);
                al[i][0] = __float_as_uint(Al[m  ][kb + tg]);
                al[i][1] = __float_as_uint(Al[m+8][kb + tg]);
                al[i][2] = __float_as_uint(Al[m  ][kb + tg + 4]);
                al[i][3] = __float_as_uint(Al[m+8][kb + tg + 4]);
            }
            #pragma unroll
            for (int j = 0; j < 4; j++) {
                int n = wn*32 + j*8 + g;
                bh[j][0] = __float_as_uint(Bh[kb + tg    ][n]);
                bh[j][1] = __float_as_uint(Bh[kb + tg + 4][n]);
                bl[j][0] = __float_as_uint(Bl[kb + tg    ][n]);
                bl[j][1] = __float_as_uint(Bl[kb + tg + 4][n]);
            }
            #pragma unroll
            for (int i = 0; i < 4; i++)
                #pragma unroll
                for (int j = 0; j < 4; j++) {
                    asm volatile(
                        "mma.sync.aligned.m16n8k8.row.col.f32.tf32.tf32.f32 "
                        "{%0,%1,%2,%3}, {%4,%5,%6,%7}, {%8,%9}, {%0,%1,%2,%3};"
                        : "+f"(acc[i][j][0]), "+f"(acc[i][j][1]),
                          "+f"(acc[i][j][2]), "+f"(acc[i][j][3])
                        : "r"(al[i][0]), "r"(al[i][1]), "r"(al[i][2]), "r"(al[i][3]),
                          "r"(bh[j][0]), "r"(bh[j][1]));
                    asm volatile(
                        "mma.sync.aligned.m16n8k8.row.col.f32.tf32.tf32.f32 "
                        "{%0,%1,%2,%3}, {%4,%5,%6,%7}, {%8,%9}, {%0,%1,%2,%3};"
                        : "+f"(acc[i][j][0]), "+f"(acc[i][j][1]),
                          "+f"(acc[i][j][2]), "+f"(acc[i][j][3])
                        : "r"(ah[i][0]), "r"(ah[i][1]), "r"(ah[i][2]), "r"(ah[i][3]),
                          "r"(bl[j][0]), "r"(bl[j][1]));
                    asm volatile(
                        "mma.sync.aligned.m16n8k8.row.col.f32.tf32.tf32.f32 "
                        "{%0,%1,%2,%3}, {%4,%5,%6,%7}, {%8,%9}, {%0,%1,%2,%3};"
                        : "+f"(acc[i][j][0]), "+f"(acc[i][j][1]),
                          "+f"(acc[i][j][2]), "+f"(acc[i][j][3])
                        : "r"(ah[i][0]), "r"(ah[i][1]), "r"(ah[i][2]), "r"(ah[i][3]),
                          "r"(bh[j][0]), "r"(bh[j][1]));
                }
        }
    }

    #pragma unroll
    for (int i = 0; i < 4; i++) {
        int r0 = m0 + wm*64 + i*16 + g;
        int r1 = r0 + 8;
        #pragma unroll
        for (int j = 0; j < 4; j++) {
            int col = n0 + wn*32 + j*8 + 2*tg;
            if (EPI == 0) {
                *(float2*)&C[(size_t)r0*N + col] = make_float2(acc[i][j][0], acc[i][j][1]);
                *(float2*)&C[(size_t)r1*N + col] = make_float2(acc[i][j][2], acc[i][j][3]);
            } else if (EPI == 1) {
                float2 c0 = *(float2*)&C[(size_t)r0*N + col];
                float2 c1 = *(float2*)&C[(size_t)r1*N + col];
                const float* g0 = aux + (size_t)(r0 >> 8) * MODW + col;
                const float* g1 = aux + (size_t)(r1 >> 8) * MODW + col;
                c0.x += acc[i][j][0] * g0[0]; c0.y += acc[i][j][1] * g0[1];
                c1.x += acc[i][j][2] * g1[0]; c1.y += acc[i][j][3] * g1[1];
                *(float2*)&C[(size_t)r0*N + col] = c0;
                *(float2*)&C[(size_t)r1*N + col] = c1;
            } else {
                const float* u0 = aux + (size_t)r0*N + col;
                const float* u1 = aux + (size_t)r1*N + col;
                float v;
                v = acc[i][j][0]; float o0 = u0[0] * (v / (1.f + __expf(-v)));
                v = acc[i][j][1]; float o1 = u0[1] * (v / (1.f + __expf(-v)));
                v = acc[i][j][2]; float o2 = u1[0] * (v / (1.f + __expf(-v)));
                v = acc[i][j][3]; float o3 = u1[1] * (v / (1.f + __expf(-v)));
                *(float2*)&C[(size_t)r0*N + col] = make_float2(o0, o1);
                *(float2*)&C[(size_t)r1*N + col] = make_float2(o2, o3);
            }
        }
    }
}

// ---------------- qkv split + per-head RMSNorm ----------------
__global__ void splitnorm_kernel(const float* __restrict__ sq, const float* __restrict__ sk) {
    int s = blockIdx.x, hh = blockIdx.y, d = threadIdx.x;
    const float* base = g_qkv + (size_t)s * (3*DMODEL) + hh * DHEAD;
    float qv = base[d], kv = base[DMODEL + d], vv = base[2*DMODEL + d];
    __shared__ float red[4];
    float qs = qv * qv, ks = kv * kv;
    #pragma unroll
    for (int o = 16; o > 0; o >>= 1) {
        qs += __shfl_xor_sync(0xffffffffu, qs, o);
        ks += __shfl_xor_sync(0xffffffffu, ks, o);
    }
    if ((d & 31) == 0) { red[d >> 5] = qs; red[2 + (d >> 5)] = ks; }
    __syncthreads();
    float qr = 1.f / (sqrtf((red[0]+red[1]) * (1.f/64.f)) + EPSV);
    float kr = 1.f / (sqrtf((red[2]+red[3]) * (1.f/64.f)) + EPSV);
    size_t o = ((size_t)hh * SDIM + s) * DHEAD + d;
    g_qn[o] = qv * qr * sq[d];
    g_kn[o] = kv * kr * sk[d];
    g_vv[o] = vv;
}

// ---------------- flash attention (block-causal, unscaled logits) ----------------
__global__ void __launch_bounds__(256) flash_kernel() {
    extern __shared__ float sm[];
    float* Qs = sm;            // Qs[d*65+i]
    float* Ks = sm + 4160;     // Ks[d*65+j]
    float* Vs = sm + 8320;     // Vs[j*65+dc]
    float* Ps = sm + 12480;    // Ps[j*65+i]
    int qb = blockIdx.x, hh = blockIdx.y;
    int q0 = qb * 64;
    int nk = ((qb >> 2) + 1) * 4;
    int tid = threadIdx.x, tx = tid & 15, ty = tid >> 4;
    int ri = ty * 4, cj = tx * 4;

    const float* qbase = g_qn + ((size_t)hh * SDIM + q0) * DHEAD;
    for (int idx = tid; idx < 4096; idx += 256) {
        int i = idx >> 6, d = idx & 63;
        Qs[d*65 + i] = qbase[idx];
    }
    float mm[4], ll[4], ov[4][4];
    #pragma unroll
    for (int i = 0; i < 4; i++) {
        mm[i] = -1e30f; ll[i] = 0.f;
        #pragma unroll
        for (int j = 0; j < 4; j++) ov[i][j] = 0.f;
    }

    for (int kt = 0; kt < nk; kt++) {
        const float* kbase = g_kn + ((size_t)hh * SDIM + kt*64) * DHEAD;
        const float* vbase = g_vv + ((size_t)hh * SDIM + kt*64) * DHEAD;
        __syncthreads();
        for (int idx = tid; idx < 4096; idx += 256) {
            int j = idx >> 6, d = idx & 63;
            Ks[d*65 + j] = kbase[idx];
            Vs[j*65 + d] = vbase[idx];
        }
        __syncthreads();

        float sc[4][4];
        #pragma unroll
        for (int i = 0; i < 4; i++)
            #pragma unroll
            for (int j = 0; j < 4; j++) sc[i][j] = 0.f;
        #pragma unroll 4
        for (int d = 0; d < 64; d++) {
            float a[4], b[4];
            #pragma unroll
            for (int i = 0; i < 4; i++) a[i] = Qs[d*65 + ri + i];
            #pragma unroll
            for (int j = 0; j < 4; j++) b[j] = Ks[d*65 + cj + j];
            #pragma unroll
            for (int i = 0; i < 4; i++)
                #pragma unroll
                for (int j = 0; j < 4; j++) sc[i][j] += a[i] * b[j];
        }
        #pragma unroll
        for (int i = 0; i < 4; i++) {
            float mx = fmaxf(fmaxf(sc[i][0], sc[i][1]), fmaxf(sc[i][2], sc[i][3]));
            #pragma unroll
            for (int o = 1; o < 16; o <<= 1) mx = fmaxf(mx, __shfl_xor_sync(0xffffffffu, mx, o));
            float mn = fmaxf(mm[i], mx);
            float scale = __expf(mm[i] - mn);
            float rs = 0.f;
            #pragma unroll
            for (int j = 0; j < 4; j++) {
                float p = __expf(sc[i][j] - mn);
                sc[i][j] = p; rs += p;
            }
            #pragma unroll
            for (int o = 1; o < 16; o <<= 1) rs += __shfl_xor_sync(0xffffffffu, rs, o);
            ll[i] = ll[i] * scale + rs;
            mm[i] = mn;
            #pragma unroll
            for (int j = 0; j < 4; j++) ov[i][j] *= scale;
        }
        #pragma unroll
        for (int i = 0; i < 4; i++)
            #pragma unroll
            for (int j = 0; j < 4; j++)
                Ps[(cj + j)*65 + ri + i] = sc[i][j];
        __syncthreads();
        #pragma unroll 4
        for (int j = 0; j < 64; j++) {
            float a[4], b[4];
            #pragma unroll
            for (int i = 0; i < 4; i++) a[i] = Ps[j*65 + ri + i];
            #pragma unroll
            for (int jc = 0; jc < 4; jc++) b[jc] = Vs[j*65 + cj + jc];
            #pragma unroll
            for (int i = 0; i < 4; i++)
                #pragma unroll
                for (int jc = 0; jc < 4; jc++) ov[i][jc] += a[i] * b[jc];
        }
    }
    #pragma unroll
    for (int i = 0; i < 4; i++) {
        float inv = 1.f / ll[i];
        int row = q0 + ri + i;
        #pragma unroll
        for (int j = 0; j < 4; j++)
            g_z[(size_t)row * DMODEL + hh*DHEAD + cj + j] = ov[i][j] * inv;
    }
}

// ---------------- output projection + unpatchify ----------------
__global__ void outproj_kernel(const float* __restrict__ Wout, const float* __restrict__ bout,
                               float* __restrict__ out) {
    __shared__ float row[DMODEL];
    int s = blockIdx.x, tid = threadIdx.x;
    for (int i = tid; i < DMODEL; i += 64) row[i] = g_h[(size_t)s * DMODEL + i];
    __syncthreads();
    if (tid < 48) {
        float acc = bout[tid];
        for (int k = 0; k < DMODEL; k++) acc += row[k] * Wout[k*48 + tid];
        int t = s >> 8, p = s & 255, oy = p >> 4, ox = p & 15;
        int c = tid >> 4, pi = (tid >> 2) & 3, pj = tid & 3;
        out[((t*3 + c)*64 + oy*4 + pi)*64 + ox*4 + pj] = acc;
    }
}

// ---------------- host ----------------
extern "C" void kernel_launch(void* const* d_in, const int* in_sizes, int n_in,
                              void* d_out, int out_size) {
    const float* x      = (const float*)d_in[0];
    const int*   actions= (const int*)  d_in[1];
    const float* ts     = (const float*)d_in[2];
    const float* conv_w = (const float*)d_in[3];
    const float* conv_b = (const float*)d_in[4];
    const float* pe     = (const float*)d_in[5];
    const float* ae     = (const float*)d_in[6];
    const float* Wmod   = (const float*)d_in[7];
    const float* bmod   = (const float*)d_in[8];
    const float* s1     = (const float*)d_in[9];
    const float* Wqkv   = (const float*)d_in[10];
    const float* Wo     = (const float*)d_in[11];
    const float* sq     = (const float*)d_in[12];
    const float* sk     = (const float*)d_in[13];
    const float* s2     = (const float*)d_in[14];
    const float* Wup    = (const float*)d_in[15];
    const float* Wgate  = (const float*)d_in[16];
    const float* Wdown  = (const float*)d_in[17];
    const float* s_final= (const float*)d_in[18];
    const float* Wmf    = (const float*)d_in[19];
    const float* bmf    = (const float*)d_in[20];
    const float* Wout   = (const float*)d_in[21];
    const float* bout   = (const float*)d_in[22];
    float* out = (float*)d_out;

    float *p_tokens, *p_cond, *p_mod, *p_h, *p_qkv, *p_z, *p_u, *p_act, *p_mf;
    cudaGetSymbolAddress((void**)&p_tokens, g_tokens);
    cudaGetSymbolAddress((void**)&p_cond,   g_cond);
    cudaGetSymbolAddress((void**)&p_mod,    g_mod);
    cudaGetSymbolAddress((void**)&p_h,      g_h);
    cudaGetSymbolAddress((void**)&p_qkv,    g_qkv);
    cudaGetSymbolAddress((void**)&p_z,      g_z);
    cudaGetSymbolAddress((void**)&p_u,      g_u);
    cudaGetSymbolAddress((void**)&p_act,    g_act);
    cudaGetSymbolAddress((void**)&p_mf,     g_mf);

    cudaFuncSetAttribute(flash_kernel, cudaFuncAttributeMaxDynamicSharedMemorySize, 66560);

    patchify_kernel<<<SDIM, 256>>>(x, conv_w, conv_b, pe);
    cond_kernel<<<TFRM, 256>>>(actions, ts, ae);

    for (int l = 0; l < NLAYER; l++) {
        const float* Wm  = Wmod  + (size_t)l * DMODEL * MODW;
        const float* bm  = bmod  + (size_t)l * MODW;
        const float* s1l = s1    + (size_t)l * DMODEL;
        const float* Wq  = Wqkv  + (size_t)l * DMODEL * 3*DMODEL;
        const float* Wol = Wo    + (size_t)l * DMODEL * DMODEL;
        const float* sql = sq    + (size_t)l * DHEAD;
        const float* skl = sk    + (size_t)l * DHEAD;
        const float* s2l = s2    + (size_t)l * DMODEL;
        const float* Wul = Wup   + (size_t)l * DMODEL * EXPD;
        const float* Wgl = Wgate + (size_t)l * DMODEL * EXPD;
        const float* Wdl = Wdown + (size_t)l * EXPD * DMODEL;

        smallm_gemm<<<MODW/128, 256>>>(p_cond, Wm, bm, p_mod, MODW);
        modulate_kernel<<<SDIM, 256>>>(p_tokens, p_h, s1l, p_mod, MODW, 0, 768);
        gemm_tc<0><<<dim3(3*DMODEL/128, SDIM/128), 256>>>(p_h, Wq, p_qkv, SDIM, 3*DMODEL, DMODEL, nullptr);
        splitnorm_kernel<<<dim3(SDIM, NHEAD), 64>>>(sql, skl);
        flash_kernel<<<dim3(SDIM/64, NHEAD), 256, 66560>>>();
        gemm_tc<1><<<dim3(DMODEL/128, SDIM/128), 256>>>(p_z, Wol, p_tokens, SDIM, DMODEL, DMODEL, p_mod + 1536);
        modulate_kernel<<<SDIM, 256>>>(p_tokens, p_h, s2l, p_mod, MODW, 2304, 3072);
        gemm_tc<0><<<dim3(EXPD/128, SDIM/128), 256>>>(p_h, Wul, p_u, SDIM, EXPD, DMODEL, nullptr);
        gemm_tc<2><<<dim3(EXPD/128, SDIM/128), 256>>>(p_h, Wgl, p_act, SDIM, EXPD, DMODEL, p_u);
        gemm_tc<1><<<dim3(DMODEL/128, SDIM/128), 256>>>(p_act, Wdl, p_tokens, SDIM, DMODEL, EXPD, p_mod + 3840);
    }

    smallm_gemm<<<2*DMODEL/128, 256>>>(p_cond, Wmf, bmf, p_mf, 2*DMODEL);
    modulate_kernel<<<SDIM, 256>>>(p_tokens, p_h, s_final, p_mf, 2*DMODEL, 0, 768);
    outproj_kernel<<<SDIM, 64>>>(Wout, bout, out);
}

// round 5
// speedup vs baseline: 1.7458x; 1.5187x over previous
#include <cuda_runtime.h>
#include <cuda_bf16.h>
#include <math.h>
#include <stdint.h>

// ---------------- constants ----------------
#define DMODEL 768
#define NHEAD  12
#define DHEAD  64
#define NLAYER 4
#define PPF    256
#define SDIM   2048   // TF * PPF
#define TFRM   8
#define EXPD   3072   // EXP * D
#define MODW   4608   // 6*D
#define EPSV   1e-6f

// weight plane layout (transposed [N][K] bf16), per-layer stride and offsets
#define LWSTRIDE 9437184
#define OFF_QKV  0
#define OFF_WO   1769472
#define OFF_UP   2359296
#define OFF_GATE 4718592
#define OFF_DOWN 7077888

// ---------------- scratch ----------------
__device__ float g_tokens[SDIM*DMODEL];
__device__ float g_cond[TFRM*DMODEL];
__device__ float g_mod[TFRM*MODW];
__device__ float g_h[SDIM*DMODEL];
__device__ float g_qkv[SDIM*3*DMODEL];
__device__ float g_qn[NHEAD*SDIM*DHEAD];
__device__ float g_kn[NHEAD*SDIM*DHEAD];
__device__ float g_vv[NHEAD*SDIM*DHEAD];
__device__ float g_u[SDIM*EXPD];
__device__ float g_mf[TFRM*2*DMODEL];

__device__ __nv_bfloat16 g_whi[4*LWSTRIDE];
__device__ __nv_bfloat16 g_wlo[4*LWSTRIDE];
__device__ __nv_bfloat16 g_hh[SDIM*DMODEL],  g_hl[SDIM*DMODEL];
__device__ __nv_bfloat16 g_zh[SDIM*DMODEL],  g_zl[SDIM*DMODEL];
__device__ __nv_bfloat16 g_acth[SDIM*EXPD],  g_actl[SDIM*EXPD];

// ---------------- helpers ----------------
__device__ __forceinline__ void cp16(uint32_t d, const void* s) {
    asm volatile("cp.async.cg.shared.global [%0], [%1], 16;" :: "r"(d), "l"(s));
}
__device__ __forceinline__ void ldsm4(uint32_t& r0, uint32_t& r1, uint32_t& r2, uint32_t& r3, uint32_t a) {
    asm volatile("ldmatrix.sync.aligned.m8n8.x4.shared.b16 {%0,%1,%2,%3}, [%4];"
                 : "=r"(r0), "=r"(r1), "=r"(r2), "=r"(r3) : "r"(a));
}
__device__ __forceinline__ void mma16816(float* d, const uint32_t* a, const uint32_t* b) {
    asm volatile("mma.sync.aligned.m16n8k16.row.col.f32.bf16.bf16.f32 "
        "{%0,%1,%2,%3}, {%4,%5,%6,%7}, {%8,%9}, {%0,%1,%2,%3};"
        : "+f"(d[0]), "+f"(d[1]), "+f"(d[2]), "+f"(d[3])
        : "r"(a[0]), "r"(a[1]), "r"(a[2]), "r"(a[3]), "r"(b[0]), "r"(b[1]));
}

// ---------------- weight transpose + bf16 hi/lo split:  W[K][N] -> Wt[N][K] ----------------
__global__ void wsplit_kernel(const float* __restrict__ W, __nv_bfloat16* __restrict__ oh,
                              __nv_bfloat16* __restrict__ ol, int K, int N) {
    __shared__ float t[32][33];
    int n0 = blockIdx.x*32, k0 = blockIdx.y*32;
    int tx = threadIdx.x, ty = threadIdx.y;
    #pragma unroll
    for (int r = ty; r < 32; r += 8) t[r][tx] = W[(size_t)(k0+r)*N + n0+tx];
    __syncthreads();
    #pragma unroll
    for (int r = ty; r < 32; r += 8) {
        float v = t[tx][r];
        __nv_bfloat16 h = __float2bfloat16(v);
        size_t o = (size_t)(n0+r)*K + k0+tx;
        oh[o] = h; ol[o] = __float2bfloat16(v - __bfloat162float(h));
    }
}

// ---------------- patchify: conv k5 s4 p2 + pos-embed ----------------
__global__ void patchify_kernel(const float* __restrict__ x, const float* __restrict__ cw,
                                const float* __restrict__ cb, const float* __restrict__ pe) {
    int s = blockIdx.x;
    int t = s >> 8, p = s & 255, oy = p >> 4, ox = p & 15;
    __shared__ float patch[75];
    int tid = threadIdx.x;
    if (tid < 75) {
        int c = tid / 25, rem = tid % 25, r = rem / 5, w = rem % 5;
        int iy = oy*4 - 2 + r, ix = ox*4 - 2 + w;
        float v = 0.f;
        if (iy >= 0 && iy < 64 && ix >= 0 && ix < 64)
            v = x[((t*3 + c)*64 + iy)*64 + ix];
        patch[tid] = v;
    }
    __syncthreads();
    for (int d = tid; d < DMODEL; d += 256) {
        float acc = cb[d];
        const float* w = cw + d*75;
        #pragma unroll
        for (int i = 0; i < 75; i++) acc += patch[i] * w[i];
        g_tokens[s*DMODEL + d] = acc + pe[p*DMODEL + d];
    }
}

// ---------------- conditioning ----------------
__global__ void cond_kernel(const int* __restrict__ actions, const float* __restrict__ ts,
                            const float* __restrict__ ae) {
    int f = blockIdx.x;
    int a = actions[f];
    float tsv = ts[f];
    int ti = (int)(tsv * 1000.0f);
    if (ti > 999) ti = 999;
    float tif = (float)ti;
    for (int d = threadIdx.x; d < DMODEL; d += blockDim.x) {
        int j = (d < 384) ? d : d - 384;
        float th = powf(500.0f, -((float)j) / 384.0f);
        float ang = tif * th;
        float te = (d < 384) ? sinf(ang) : cosf(ang);
        float c = te + ae[a*DMODEL + d];
        g_cond[f*DMODEL + d] = c / (1.f + expf(-c));
    }
}

// ---------------- small-M GEMM ----------------
__global__ void smallm_gemm(const float* __restrict__ A, const float* __restrict__ B,
                            const float* __restrict__ bias, float* __restrict__ C, int N) {
    __shared__ float As[8*DMODEL];
    int tid = threadIdx.x;
    for (int i = tid; i < 8*DMODEL; i += 256) As[i] = A[i];
    __syncthreads();
    int col = tid & 127, rg = tid >> 7;
    int n = blockIdx.x * 128 + col;
    float acc0 = 0, acc1 = 0, acc2 = 0, acc3 = 0;
    int rb = rg * 4;
    for (int k = 0; k < DMODEL; k++) {
        float bv = B[(size_t)k * N + n];
        acc0 += As[(rb+0)*DMODEL + k] * bv;
        acc1 += As[(rb+1)*DMODEL + k] * bv;
        acc2 += As[(rb+2)*DMODEL + k] * bv;
        acc3 += As[(rb+3)*DMODEL + k] * bv;
    }
    float bs = bias[n];
    C[(rb+0)*N + n] = acc0 + bs;
    C[(rb+1)*N + n] = acc1 + bs;
    C[(rb+2)*N + n] = acc2 + bs;
    C[(rb+3)*N + n] = acc3 + bs;
}

// ---------------- RMSNorm + AdaLN modulate (writes fp32 + bf16 hi/lo planes) ----------------
__global__ void modulate_kernel(const float* __restrict__ in, float* __restrict__ out,
                                const float* __restrict__ sa, const float* __restrict__ mod,
                                int mstride, int off_sc, int off_b) {
    int s = blockIdx.x, tid = threadIdx.x, f = s >> 8;
    const float* row = in + (size_t)s * DMODEL;
    float v0 = row[tid], v1 = row[tid+256], v2 = row[tid+512];
    float ss = v0*v0 + v1*v1 + v2*v2;
    __shared__ float red[8];
    #pragma unroll
    for (int o = 16; o > 0; o >>= 1) ss += __shfl_xor_sync(0xffffffffu, ss, o);
    if ((tid & 31) == 0) red[tid >> 5] = ss;
    __syncthreads();
    float tot = 0.f;
    #pragma unroll
    for (int w = 0; w < 8; w++) tot += red[w];
    float rinv = 1.f / (sqrtf(tot * (1.f/768.f)) + EPSV);
    const float* mrow = mod + f * mstride;
    float* orow = out + (size_t)s * DMODEL;
    size_t base = (size_t)s * DMODEL;
    #pragma unroll
    for (int c = 0; c < 3; c++) {
        int d = tid + c*256;
        float v = (c == 0) ? v0 : (c == 1 ? v1 : v2);
        float o = v * rinv * sa[d] * (1.f + mrow[off_sc + d]) + mrow[off_b + d];
        orow[d] = o;
        __nv_bfloat16 h = __float2bfloat16(o);
        g_hh[base + d] = h;
        g_hl[base + d] = __float2bfloat16(o - __bfloat162float(h));
    }
}

// ---------------- bf16 3-term split tensor-core GEMM ----------------
// A planes [M][K] bf16 hi/lo; B planes [N][K] bf16 hi/lo (k-contiguous).
// EPI 0: C = acc                  EPI 1: C += acc * aux[frame(m)*MODW + n]
// EPI 2: Oh/Ol = bf16split(aux[m*N+n] * silu(acc))   (C unused)
#define KROW 24          // bf16 per smem row (16 data + 8 pad) = 48B
#define PL_SZ 3072       // 128*KROW bf16 per plane
#define PL_B  6144       // bytes per plane
#define ST_B  24576      // bytes per stage (4 planes)

template<int EPI>
__global__ void __launch_bounds__(256) gemm_bf16(
    const __nv_bfloat16* __restrict__ Agh, const __nv_bfloat16* __restrict__ Agl,
    const __nv_bfloat16* __restrict__ Bgh, const __nv_bfloat16* __restrict__ Bgl,
    float* __restrict__ C, int M, int N, int K,
    const float* __restrict__ aux,
    __nv_bfloat16* __restrict__ Oh, __nv_bfloat16* __restrict__ Ol)
{
    extern __shared__ __align__(16) __nv_bfloat16 smem[];   // 3 stages x 4 planes x 3072
    int tid = threadIdx.x, lane = tid & 31, wid = tid >> 5;
    int m0 = blockIdx.y * 128, n0 = blockIdx.x * 128;
    int wm = wid >> 2, wn = wid & 3, g = lane >> 2, tg = lane & 3;

    float acc[4][4][4];
    #pragma unroll
    for (int i = 0; i < 4; i++)
        #pragma unroll
        for (int j = 0; j < 4; j++)
            #pragma unroll
            for (int c = 0; c < 4; c++) acc[i][j][c] = 0.f;

    // cp.async mapping: thread t loads row r = t>>1, 16B-half hf of each plane
    int r = tid >> 1, hf = tid & 1;
    const __nv_bfloat16* srcA0 = Agh + (size_t)(m0 + r) * K + hf*8;
    const __nv_bfloat16* srcA1 = Agl + (size_t)(m0 + r) * K + hf*8;
    const __nv_bfloat16* srcB0 = Bgh + (size_t)(n0 + r) * K + hf*8;
    const __nv_bfloat16* srcB1 = Bgl + (size_t)(n0 + r) * K + hf*8;
    uint32_t sbase = (uint32_t)__cvta_generic_to_shared(smem);
    uint32_t doff = r*48 + hf*16;

    int NK = K >> 4;

    #define PF(st, kc) { \
        uint32_t b_ = sbase + (st)*ST_B + doff; \
        cp16(b_,            srcA0 + (kc)); \
        cp16(b_ +   PL_B,   srcA1 + (kc)); \
        cp16(b_ + 2*PL_B,   srcB0 + (kc)); \
        cp16(b_ + 3*PL_B,   srcB1 + (kc)); \
        asm volatile("cp.async.commit_group;"); }

    PF(0, 0); PF(1, 16); PF(2, 32);

    // ldmatrix lane address components
    int a_row = (lane & 7) + ((lane >> 3) & 1) * 8;
    int a_kb  = ((lane >> 4) & 1) * 16;
    int b_row = (lane & 7) + ((lane >> 4) & 1) * 8;
    int b_kb  = ((lane >> 3) & 1) * 16;
    uint32_t aoffA = (uint32_t)(wm*64 + a_row) * 48 + a_kb;
    uint32_t aoffB = (uint32_t)(wn*32 + b_row) * 48 + b_kb;

    int st = 0;
    for (int ks = 0; ks < NK; ks++) {
        int rem = NK - 1 - ks;
        if (rem >= 2)      asm volatile("cp.async.wait_group 2;");
        else if (rem == 1) asm volatile("cp.async.wait_group 1;");
        else               asm volatile("cp.async.wait_group 0;");
        __syncthreads();
        uint32_t base = sbase + st*ST_B;
        uint32_t bh[4][2], bl[4][2];
        #pragma unroll
        for (int jp = 0; jp < 2; jp++) {
            uint32_t ad = base + 2*PL_B + aoffB + jp*768;
            ldsm4(bh[2*jp][0], bh[2*jp][1], bh[2*jp+1][0], bh[2*jp+1][1], ad);
            ldsm4(bl[2*jp][0], bl[2*jp][1], bl[2*jp+1][0], bl[2*jp+1][1], ad + PL_B);
        }
        #pragma unroll
        for (int i = 0; i < 4; i++) {
            uint32_t ah[4], al[4];
            uint32_t ad = base + aoffA + i*768;
            ldsm4(ah[0], ah[1], ah[2], ah[3], ad);
            ldsm4(al[0], al[1], al[2], al[3], ad + PL_B);
            #pragma unroll
            for (int j = 0; j < 4; j++) {
                mma16816(acc[i][j], al, bh[j]);
                mma16816(acc[i][j], ah, bl[j]);
                mma16816(acc[i][j], ah, bh[j]);
            }
        }
        __syncthreads();
        if (ks + 3 < NK) PF(st, (ks+3)*16);
        st++; if (st == 3) st = 0;
    }
    #undef PF

    #pragma unroll
    for (int i = 0; i < 4; i++) {
        int r0 = m0 + wm*64 + i*16 + g;
        int r1 = r0 + 8;
        #pragma unroll
        for (int j = 0; j < 4; j++) {
            int col = n0 + wn*32 + j*8 + 2*tg;
            if (EPI == 0) {
                *(float2*)&C[(size_t)r0*N + col] = make_float2(acc[i][j][0], acc[i][j][1]);
                *(float2*)&C[(size_t)r1*N + col] = make_float2(acc[i][j][2], acc[i][j][3]);
            } else if (EPI == 1) {
                float2 c0 = *(float2*)&C[(size_t)r0*N + col];
                float2 c1 = *(float2*)&C[(size_t)r1*N + col];
                const float* g0 = aux + (size_t)(r0 >> 8) * MODW + col;
                const float* g1 = aux + (size_t)(r1 >> 8) * MODW + col;
                c0.x += acc[i][j][0] * g0[0]; c0.y += acc[i][j][1] * g0[1];
                c1.x += acc[i][j][2] * g1[0]; c1.y += acc[i][j][3] * g1[1];
                *(float2*)&C[(size_t)r0*N + col] = c0;
                *(float2*)&C[(size_t)r1*N + col] = c1;
            } else {
                const float* u0 = aux + (size_t)r0*N + col;
                const float* u1 = aux + (size_t)r1*N + col;
                float v, o0, o1, o2, o3;
                v = acc[i][j][0]; o0 = u0[0] * (v / (1.f + __expf(-v)));
                v = acc[i][j][1]; o1 = u0[1] * (v / (1.f + __expf(-v)));
                v = acc[i][j][2]; o2 = u1[0] * (v / (1.f + __expf(-v)));
                v = acc[i][j][3]; o3 = u1[1] * (v / (1.f + __expf(-v)));
                __nv_bfloat16 h0 = __float2bfloat16(o0), h1 = __float2bfloat16(o1);
                __nv_bfloat16 h2 = __float2bfloat16(o2), h3 = __float2bfloat16(o3);
                __nv_bfloat162 p;
                p.x = h0; p.y = h1; *(__nv_bfloat162*)&Oh[(size_t)r0*N + col] = p;
                p.x = h2; p.y = h3; *(__nv_bfloat162*)&Oh[(size_t)r1*N + col] = p;
                p.x = __float2bfloat16(o0 - __bfloat162float(h0));
                p.y = __float2bfloat16(o1 - __bfloat162float(h1));
                *(__nv_bfloat162*)&Ol[(size_t)r0*N + col] = p;
                p.x = __float2bfloat16(o2 - __bfloat162float(h2));
                p.y = __float2bfloat16(o3 - __bfloat162float(h3));
                *(__nv_bfloat162*)&Ol[(size_t)r1*N + col] = p;
            }
        }
    }
}

// ---------------- qkv split + per-head RMSNorm ----------------
__global__ void splitnorm_kernel(const float* __restrict__ sq, const float* __restrict__ sk) {
    int s = blockIdx.x, hh = blockIdx.y, d = threadIdx.x;
    const float* base = g_qkv + (size_t)s * (3*DMODEL) + hh * DHEAD;
    float qv = base[d], kv = base[DMODEL + d], vv = base[2*DMODEL + d];
    __shared__ float red[4];
    float qs = qv * qv, ks = kv * kv;
    #pragma unroll
    for (int o = 16; o > 0; o >>= 1) {
        qs += __shfl_xor_sync(0xffffffffu, qs, o);
        ks += __shfl_xor_sync(0xffffffffu, ks, o);
    }
    if ((d & 31) == 0) { red[d >> 5] = qs; red[2 + (d >> 5)] = ks; }
    __syncthreads();
    float qr = 1.f / (sqrtf((red[0]+red[1]) * (1.f/64.f)) + EPSV);
    float kr = 1.f / (sqrtf((red[2]+red[3]) * (1.f/64.f)) + EPSV);
    size_t o = ((size_t)hh * SDIM + s) * DHEAD + d;
    g_qn[o] = qv * qr * sq[d];
    g_kn[o] = kv * kr * sk[d];
    g_vv[o] = vv;
}

// ---------------- flash attention (block-causal, unscaled logits) ----------------
__global__ void __launch_bounds__(256) flash_kernel() {
    extern __shared__ float sm[];
    float* Qs = sm;            // Qs[d*65+i]
    float* Ks = sm + 4160;     // Ks[d*65+j]
    float* Vs = sm + 8320;     // Vs[j*65+dc]
    float* Ps = sm + 12480;    // Ps[j*65+i]
    int qb = blockIdx.x, hh = blockIdx.y;
    int q0 = qb * 64;
    int nk = ((qb >> 2) + 1) * 4;
    int tid = threadIdx.x, tx = tid & 15, ty = tid >> 4;
    int ri = ty * 4, cj = tx * 4;

    const float* qbase = g_qn + ((size_t)hh * SDIM + q0) * DHEAD;
    for (int idx = tid; idx < 4096; idx += 256) {
        int i = idx >> 6, d = idx & 63;
        Qs[d*65 + i] = qbase[idx];
    }
    float mm[4], ll[4], ov[4][4];
    #pragma unroll
    for (int i = 0; i < 4; i++) {
        mm[i] = -1e30f; ll[i] = 0.f;
        #pragma unroll
        for (int j = 0; j < 4; j++) ov[i][j] = 0.f;
    }

    for (int kt = 0; kt < nk; kt++) {
        const float* kbase = g_kn + ((size_t)hh * SDIM + kt*64) * DHEAD;
        const float* vbase = g_vv + ((size_t)hh * SDIM + kt*64) * DHEAD;
        __syncthreads();
        for (int idx = tid; idx < 4096; idx += 256) {
            int j = idx >> 6, d = idx & 63;
            Ks[d*65 + j] = kbase[idx];
            Vs[j*65 + d] = vbase[idx];
        }
        __syncthreads();

        float sc[4][4];
        #pragma unroll
        for (int i = 0; i < 4; i++)
            #pragma unroll
            for (int j = 0; j < 4; j++) sc[i][j] = 0.f;
        #pragma unroll 4
        for (int d = 0; d < 64; d++) {
            float a[4], b[4];
            #pragma unroll
            for (int i = 0; i < 4; i++) a[i] = Qs[d*65 + ri + i];
            #pragma unroll
            for (int j = 0; j < 4; j++) b[j] = Ks[d*65 + cj + j];
            #pragma unroll
            for (int i = 0; i < 4; i++)
                #pragma unroll
                for (int j = 0; j < 4; j++) sc[i][j] += a[i] * b[j];
        }
        #pragma unroll
        for (int i = 0; i < 4; i++) {
            float mx = fmaxf(fmaxf(sc[i][0], sc[i][1]), fmaxf(sc[i][2], sc[i][3]));
            #pragma unroll
            for (int o = 1; o < 16; o <<= 1) mx = fmaxf(mx, __shfl_xor_sync(0xffffffffu, mx, o));
            float mn = fmaxf(mm[i], mx);
            float scale = __expf(mm[i] - mn);
            float rs = 0.f;
            #pragma unroll
            for (int j = 0; j < 4; j++) {
                float p = __expf(sc[i][j] - mn);
                sc[i][j] = p; rs += p;
            }
            #pragma unroll
            for (int o = 1; o < 16; o <<= 1) rs += __shfl_xor_sync(0xffffffffu, rs, o);
            ll[i] = ll[i] * scale + rs;
            mm[i] = mn;
            #pragma unroll
            for (int j = 0; j < 4; j++) ov[i][j] *= scale;
        }
        #pragma unroll
        for (int i = 0; i < 4; i++)
            #pragma unroll
            for (int j = 0; j < 4; j++)
                Ps[(cj + j)*65 + ri + i] = sc[i][j];
        __syncthreads();
        #pragma unroll 4
        for (int j = 0; j < 64; j++) {
            float a[4], b[4];
            #pragma unroll
            for (int i = 0; i < 4; i++) a[i] = Ps[j*65 + ri + i];
            #pragma unroll
            for (int jc = 0; jc < 4; jc++) b[jc] = Vs[j*65 + cj + jc];
            #pragma unroll
            for (int i = 0; i < 4; i++)
                #pragma unroll
                for (int jc = 0; jc < 4; jc++) ov[i][jc] += a[i] * b[jc];
        }
    }
    #pragma unroll
    for (int i = 0; i < 4; i++) {
        float inv = 1.f / ll[i];
        int row = q0 + ri + i;
        #pragma unroll
        for (int j = 0; j < 4; j++) {
            float o = ov[i][j] * inv;
            size_t idx = (size_t)row * DMODEL + hh*DHEAD + cj + j;
            __nv_bfloat16 h = __float2bfloat16(o);
            g_zh[idx] = h;
            g_zl[idx] = __float2bfloat16(o - __bfloat162float(h));
        }
    }
}

// ---------------- output projection + unpatchify ----------------
__global__ void outproj_kernel(const float* __restrict__ Wout, const float* __restrict__ bout,
                               float* __restrict__ out) {
    __shared__ float row[DMODEL];
    int s = blockIdx.x, tid = threadIdx.x;
    for (int i = tid; i < DMODEL; i += 64) row[i] = g_h[(size_t)s * DMODEL + i];
    __syncthreads();
    if (tid < 48) {
        float acc = bout[tid];
        for (int k = 0; k < DMODEL; k++) acc += row[k] * Wout[k*48 + tid];
        int t = s >> 8, p = s & 255, oy = p >> 4, ox = p & 15;
        int c = tid >> 4, pi = (tid >> 2) & 3, pj = tid & 3;
        out[((t*3 + c)*64 + oy*4 + pi)*64 + ox*4 + pj] = acc;
    }
}

// ---------------- host ----------------
#define GEMM_SMEM (3*ST_B)

extern "C" void kernel_launch(void* const* d_in, const int* in_sizes, int n_in,
                              void* d_out, int out_size) {
    const float* x      = (const float*)d_in[0];
    const int*   actions= (const int*)  d_in[1];
    const float* ts     = (const float*)d_in[2];
    const float* conv_w = (const float*)d_in[3];
    const float* conv_b = (const float*)d_in[4];
    const float* pe     = (const float*)d_in[5];
    const float* ae     = (const float*)d_in[6];
    const float* Wmod   = (const float*)d_in[7];
    const float* bmod   = (const float*)d_in[8];
    const float* s1     = (const float*)d_in[9];
    const float* Wqkv   = (const float*)d_in[10];
    const float* Wo     = (const float*)d_in[11];
    const float* sq     = (const float*)d_in[12];
    const float* sk     = (const float*)d_in[13];
    const float* s2     = (const float*)d_in[14];
    const float* Wup    = (const float*)d_in[15];
    const float* Wgate  = (const float*)d_in[16];
    const float* Wdown  = (const float*)d_in[17];
    const float* s_final= (const float*)d_in[18];
    const float* Wmf    = (const float*)d_in[19];
    const float* bmf    = (const float*)d_in[20];
    const float* Wout   = (const float*)d_in[21];
    const float* bout   = (const float*)d_in[22];
    float* out = (float*)d_out;

    float *p_tokens, *p_cond, *p_mod, *p_h, *p_qkv, *p_u, *p_mf;
    __nv_bfloat16 *p_whi, *p_wlo, *p_hh, *p_hl, *p_zh, *p_zl, *p_acth, *p_actl;
    cudaGetSymbolAddress((void**)&p_tokens, g_tokens);
    cudaGetSymbolAddress((void**)&p_cond,   g_cond);
    cudaGetSymbolAddress((void**)&p_mod,    g_mod);
    cudaGetSymbolAddress((void**)&p_h,      g_h);
    cudaGetSymbolAddress((void**)&p_qkv,    g_qkv);
    cudaGetSymbolAddress((void**)&p_u,      g_u);
    cudaGetSymbolAddress((void**)&p_mf,     g_mf);
    cudaGetSymbolAddress((void**)&p_whi,    g_whi);
    cudaGetSymbolAddress((void**)&p_wlo,    g_wlo);
    cudaGetSymbolAddress((void**)&p_hh,     g_hh);
    cudaGetSymbolAddress((void**)&p_hl,     g_hl);
    cudaGetSymbolAddress((void**)&p_zh,     g_zh);
    cudaGetSymbolAddress((void**)&p_zl,     g_zl);
    cudaGetSymbolAddress((void**)&p_acth,   g_acth);
    cudaGetSymbolAddress((void**)&p_actl,   g_actl);

    cudaFuncSetAttribute(flash_kernel, cudaFuncAttributeMaxDynamicSharedMemorySize, 66560);
    cudaFuncSetAttribute(gemm_bf16<0>, cudaFuncAttributeMaxDynamicSharedMemorySize, GEMM_SMEM);
    cudaFuncSetAttribute(gemm_bf16<1>, cudaFuncAttributeMaxDynamicSharedMemorySize, GEMM_SMEM);
    cudaFuncSetAttribute(gemm_bf16<2>, cudaFuncAttributeMaxDynamicSharedMemorySize, GEMM_SMEM);

    // ---- weight transpose + split (once per launch; part of the graph) ----
    dim3 tb(32, 8);
    for (int l = 0; l < NLAYER; l++) {
        size_t lb = (size_t)l * LWSTRIDE;
        wsplit_kernel<<<dim3(2304/32, 768/32), tb>>>(Wqkv  + (size_t)l*DMODEL*3*DMODEL, p_whi + lb + OFF_QKV,  p_wlo + lb + OFF_QKV,  768, 2304);
        wsplit_kernel<<<dim3( 768/32, 768/32), tb>>>(Wo    + (size_t)l*DMODEL*DMODEL,   p_whi + lb + OFF_WO,   p_wlo + lb + OFF_WO,   768,  768);
        wsplit_kernel<<<dim3(3072/32, 768/32), tb>>>(Wup   + (size_t)l*DMODEL*EXPD,     p_whi + lb + OFF_UP,   p_wlo + lb + OFF_UP,   768, 3072);
        wsplit_kernel<<<dim3(3072/32, 768/32), tb>>>(Wgate + (size_t)l*DMODEL*EXPD,     p_whi + lb + OFF_GATE, p_wlo + lb + OFF_GATE, 768, 3072);
        wsplit_kernel<<<dim3( 768/32, 3072/32), tb>>>(Wdown + (size_t)l*EXPD*DMODEL,    p_whi + lb + OFF_DOWN, p_wlo + lb + OFF_DOWN, 3072, 768);
    }

    patchify_kernel<<<SDIM, 256>>>(x, conv_w, conv_b, pe);
    cond_kernel<<<TFRM, 256>>>(actions, ts, ae);

    for (int l = 0; l < NLAYER; l++) {
        size_t lb = (size_t)l * LWSTRIDE;
        const float* bm  = bmod  + (size_t)l * MODW;
        const float* s1l = s1    + (size_t)l * DMODEL;
        const float* sql = sq    + (size_t)l * DHEAD;
        const float* skl = sk    + (size_t)l * DHEAD;
        const float* s2l = s2    + (size_t)l * DMODEL;

        smallm_gemm<<<MODW/128, 256>>>(p_cond, Wmod + (size_t)l*DMODEL*MODW, bm, p_mod, MODW);
        modulate_kernel<<<SDIM, 256>>>(p_tokens, p_h, s1l, p_mod, MODW, 0, 768);
        gemm_bf16<0><<<dim3(2304/128, SDIM/128), 256, GEMM_SMEM>>>(
            p_hh, p_hl, p_whi + lb + OFF_QKV, p_wlo + lb + OFF_QKV,
            p_qkv, SDIM, 2304, 768, nullptr, nullptr, nullptr);
        splitnorm_kernel<<<dim3(SDIM, NHEAD), 64>>>(sql, skl);
        flash_kernel<<<dim3(SDIM/64, NHEAD), 256, 66560>>>();
        gemm_bf16<1><<<dim3(768/128, SDIM/128), 256, GEMM_SMEM>>>(
            p_zh, p_zl, p_whi + lb + OFF_WO, p_wlo + lb + OFF_WO,
            p_tokens, SDIM, 768, 768, p_mod + 1536, nullptr, nullptr);
        modulate_kernel<<<SDIM, 256>>>(p_tokens, p_h, s2l, p_mod, MODW, 2304, 3072);
        gemm_bf16<0><<<dim3(3072/128, SDIM/128), 256, GEMM_SMEM>>>(
            p_hh, p_hl, p_whi + lb + OFF_UP, p_wlo + lb + OFF_UP,
            p_u, SDIM, 3072, 768, nullptr, nullptr, nullptr);
        gemm_bf16<2><<<dim3(3072/128, SDIM/128), 256, GEMM_SMEM>>>(
            p_hh, p_hl, p_whi + lb + OFF_GATE, p_wlo + lb + OFF_GATE,
            nullptr, SDIM, 3072, 768, p_u, p_acth, p_actl);
        gemm_bf16<1><<<dim3(768/128, SDIM/128), 256, GEMM_SMEM>>>(
            p_acth, p_actl, p_whi + lb + OFF_DOWN, p_wlo + lb + OFF_DOWN,
            p_tokens, SDIM, 768, 3072, p_mod + 3840, nullptr, nullptr);
    }

    smallm_gemm<<<2*DMODEL/128, 256>>>(p_cond, Wmf, bmf, p_mf, 2*DMODEL);
    modulate_kernel<<<SDIM, 256>>>(p_tokens, p_h, s_final, p_mf, 2*DMODEL, 0, 768);
    outproj_kernel<<<SDIM, 64>>>(Wout, bout, out);
}

// round 8
// speedup vs baseline: 2.3138x; 1.3254x over previous
#include <cuda_runtime.h>
#include <cuda_bf16.h>
#include <math.h>
#include <stdint.h>

// ---------------- constants ----------------
#define DMODEL 768
#define NHEAD  12
#define DHEAD  64
#define NLAYER 4
#define PPF    256
#define SDIM   2048   // TF * PPF
#define TFRM   8
#define EXPD   3072   // EXP * D
#define MODW   4608   // 6*D
#define EPSV   1e-6f

// weight plane layout (transposed [N][K] bf16), per-layer stride and offsets
#define LWSTRIDE 9437184
#define OFF_QKV  0
#define OFF_WO   1769472
#define OFF_UP   2359296
#define OFF_GATE 4718592
#define OFF_DOWN 7077888

// ---------------- scratch ----------------
__device__ float g_tokens[SDIM*DMODEL];
__device__ float g_cond[TFRM*DMODEL];
__device__ float g_mod[TFRM*MODW];
__device__ float g_h[SDIM*DMODEL];
__device__ float g_qkv[SDIM*3*DMODEL];
__device__ float g_u[SDIM*EXPD];
__device__ float g_mf[TFRM*2*DMODEL];

__device__ __nv_bfloat16 g_whi[4*LWSTRIDE];
__device__ __nv_bfloat16 g_wlo[4*LWSTRIDE];
__device__ __nv_bfloat16 g_hh[SDIM*DMODEL],  g_hl[SDIM*DMODEL];
__device__ __nv_bfloat16 g_zh[SDIM*DMODEL],  g_zl[SDIM*DMODEL];
__device__ __nv_bfloat16 g_acth[SDIM*EXPD],  g_actl[SDIM*EXPD];
// attention planes [h][s][64]
__device__ __nv_bfloat16 g_qph[NHEAD*SDIM*DHEAD], g_qpl[NHEAD*SDIM*DHEAD];
__device__ __nv_bfloat16 g_kph[NHEAD*SDIM*DHEAD], g_kpl[NHEAD*SDIM*DHEAD];
__device__ __nv_bfloat16 g_vph[NHEAD*SDIM*DHEAD], g_vpl[NHEAD*SDIM*DHEAD];

// ---------------- helpers ----------------
__device__ __forceinline__ void cp16(uint32_t d, const void* s) {
    asm volatile("cp.async.cg.shared.global [%0], [%1], 16;" :: "r"(d), "l"(s));
}
__device__ __forceinline__ void ldsm4(uint32_t* r, uint32_t a) {
    asm volatile("ldmatrix.sync.aligned.m8n8.x4.shared.b16 {%0,%1,%2,%3}, [%4];"
                 : "=r"(r[0]), "=r"(r[1]), "=r"(r[2]), "=r"(r[3]) : "r"(a));
}
__device__ __forceinline__ void ldsm4t(uint32_t* r, uint32_t a) {
    asm volatile("ldmatrix.sync.aligned.m8n8.x4.trans.shared.b16 {%0,%1,%2,%3}, [%4];"
                 : "=r"(r[0]), "=r"(r[1]), "=r"(r[2]), "=r"(r[3]) : "r"(a));
}
__device__ __forceinline__ void mma16816(float* d, const uint32_t* a, const uint32_t* b) {
    asm volatile("mma.sync.aligned.m16n8k16.row.col.f32.bf16.bf16.f32 "
        "{%0,%1,%2,%3}, {%4,%5,%6,%7}, {%8,%9}, {%0,%1,%2,%3};"
        : "+f"(d[0]), "+f"(d[1]), "+f"(d[2]), "+f"(d[3])
        : "r"(a[0]), "r"(a[1]), "r"(a[2]), "r"(a[3]), "r"(b[0]), "r"(b[1]));
}
__device__ __forceinline__ uint32_t pkh(float a, float b) {
    __nv_bfloat162 t; t.x = __float2bfloat16(a); t.y = __float2bfloat16(b);
    return *(uint32_t*)&t;
}
__device__ __forceinline__ uint32_t pkl(float a, float b) {
    float ra = a - __bfloat162float(__float2bfloat16(a));
    float rb = b - __bfloat162float(__float2bfloat16(b));
    return pkh(ra, rb);
}

// ---------------- weight transpose + bf16 hi/lo split ----------------
__global__ void wsplit_kernel(const float* __restrict__ W, __nv_bfloat16* __restrict__ oh,
                              __nv_bfloat16* __restrict__ ol, int K, int N) {
    __shared__ float t[32][33];
    int n0 = blockIdx.x*32, k0 = blockIdx.y*32;
    int tx = threadIdx.x, ty = threadIdx.y;
    #pragma unroll
    for (int r = ty; r < 32; r += 8) t[r][tx] = W[(size_t)(k0+r)*N + n0+tx];
    __syncthreads();
    #pragma unroll
    for (int r = ty; r < 32; r += 8) {
        float v = t[tx][r];
        __nv_bfloat16 h = __float2bfloat16(v);
        size_t o = (size_t)(n0+r)*K + k0+tx;
        oh[o] = h; ol[o] = __float2bfloat16(v - __bfloat162float(h));
    }
}

// ---------------- patchify ----------------
__global__ void patchify_kernel(const float* __restrict__ x, const float* __restrict__ cw,
                                const float* __restrict__ cb, const float* __restrict__ pe) {
    int s = blockIdx.x;
    int t = s >> 8, p = s & 255, oy = p >> 4, ox = p & 15;
    __shared__ float patch[75];
    int tid = threadIdx.x;
    if (tid < 75) {
        int c = tid / 25, rem = tid % 25, r = rem / 5, w = rem % 5;
        int iy = oy*4 - 2 + r, ix = ox*4 - 2 + w;
        float v = 0.f;
        if (iy >= 0 && iy < 64 && ix >= 0 && ix < 64)
            v = x[((t*3 + c)*64 + iy)*64 + ix];
        patch[tid] = v;
    }
    __syncthreads();
    for (int d = tid; d < DMODEL; d += 256) {
        float acc = cb[d];
        const float* w = cw + d*75;
        #pragma unroll
        for (int i = 0; i < 75; i++) acc += patch[i] * w[i];
        g_tokens[s*DMODEL + d] = acc + pe[p*DMODEL + d];
    }
}

// ---------------- conditioning ----------------
__global__ void cond_kernel(const int* __restrict__ actions, const float* __restrict__ ts,
                            const float* __restrict__ ae) {
    int f = blockIdx.x;
    int a = actions[f];
    float tsv = ts[f];
    int ti = (int)(tsv * 1000.0f);
    if (ti > 999) ti = 999;
    float tif = (float)ti;
    for (int d = threadIdx.x; d < DMODEL; d += blockDim.x) {
        int j = (d < 384) ? d : d - 384;
        float th = powf(500.0f, -((float)j) / 384.0f);
        float ang = tif * th;
        float te = (d < 384) ? sinf(ang) : cosf(ang);
        float c = te + ae[a*DMODEL + d];
        g_cond[f*DMODEL + d] = c / (1.f + expf(-c));
    }
}

// ---------------- small-M GEMM ----------------
__global__ void smallm_gemm(const float* __restrict__ A, const float* __restrict__ B,
                            const float* __restrict__ bias, float* __restrict__ C, int N) {
    __shared__ float As[8*DMODEL];
    int tid = threadIdx.x;
    for (int i = tid; i < 8*DMODEL; i += 256) As[i] = A[i];
    __syncthreads();
    int col = tid & 127, rg = tid >> 7;
    int n = blockIdx.x * 128 + col;
    float acc0 = 0, acc1 = 0, acc2 = 0, acc3 = 0;
    int rb = rg * 4;
    for (int k = 0; k < DMODEL; k++) {
        float bv = B[(size_t)k * N + n];
        acc0 += As[(rb+0)*DMODEL + k] * bv;
        acc1 += As[(rb+1)*DMODEL + k] * bv;
        acc2 += As[(rb+2)*DMODEL + k] * bv;
        acc3 += As[(rb+3)*DMODEL + k] * bv;
    }
    float bs = bias[n];
    C[(rb+0)*N + n] = acc0 + bs;
    C[(rb+1)*N + n] = acc1 + bs;
    C[(rb+2)*N + n] = acc2 + bs;
    C[(rb+3)*N + n] = acc3 + bs;
}

// ---------------- RMSNorm + AdaLN modulate (fp32 + bf16 hi/lo planes) ----------------
__global__ void modulate_kernel(const float* __restrict__ in, float* __restrict__ out,
                                const float* __restrict__ sa, const float* __restrict__ mod,
                                int mstride, int off_sc, int off_b) {
    int s = blockIdx.x, tid = threadIdx.x, f = s >> 8;
    const float* row = in + (size_t)s * DMODEL;
    float v0 = row[tid], v1 = row[tid+256], v2 = row[tid+512];
    float ss = v0*v0 + v1*v1 + v2*v2;
    __shared__ float red[8];
    #pragma unroll
    for (int o = 16; o > 0; o >>= 1) ss += __shfl_xor_sync(0xffffffffu, ss, o);
    if ((tid & 31) == 0) red[tid >> 5] = ss;
    __syncthreads();
    float tot = 0.f;
    #pragma unroll
    for (int w = 0; w < 8; w++) tot += red[w];
    float rinv = 1.f / (sqrtf(tot * (1.f/768.f)) + EPSV);
    const float* mrow = mod + f * mstride;
    float* orow = out + (size_t)s * DMODEL;
    size_t base = (size_t)s * DMODEL;
    #pragma unroll
    for (int c = 0; c < 3; c++) {
        int d = tid + c*256;
        float v = (c == 0) ? v0 : (c == 1 ? v1 : v2);
        float o = v * rinv * sa[d] * (1.f + mrow[off_sc + d]) + mrow[off_b + d];
        orow[d] = o;
        __nv_bfloat16 h = __float2bfloat16(o);
        g_hh[base + d] = h;
        g_hl[base + d] = __float2bfloat16(o - __bfloat162float(h));
    }
}

// ---------------- bf16 3-term split tensor-core GEMM ----------------
#define KROW 24
#define PL_B  6144
#define ST_B  24576

template<int EPI>
__global__ void __launch_bounds__(256) gemm_bf16(
    const __nv_bfloat16* __restrict__ Agh, const __nv_bfloat16* __restrict__ Agl,
    const __nv_bfloat16* __restrict__ Bgh, const __nv_bfloat16* __restrict__ Bgl,
    float* __restrict__ C, int M, int N, int K,
    const float* __restrict__ aux,
    __nv_bfloat16* __restrict__ Oh, __nv_bfloat16* __restrict__ Ol)
{
    extern __shared__ __align__(16) __nv_bfloat16 smem[];
    int tid = threadIdx.x, lane = tid & 31, wid = tid >> 5;
    int m0 = blockIdx.y * 128, n0 = blockIdx.x * 128;
    int wm = wid >> 2, wn = wid & 3, g = lane >> 2, tg = lane & 3;

    float acc[4][4][4];
    #pragma unroll
    for (int i = 0; i < 4; i++)
        #pragma unroll
        for (int j = 0; j < 4; j++)
            #pragma unroll
            for (int c = 0; c < 4; c++) acc[i][j][c] = 0.f;

    int r = tid >> 1, hf = tid & 1;
    const __nv_bfloat16* srcA0 = Agh + (size_t)(m0 + r) * K + hf*8;
    const __nv_bfloat16* srcA1 = Agl + (size_t)(m0 + r) * K + hf*8;
    const __nv_bfloat16* srcB0 = Bgh + (size_t)(n0 + r) * K + hf*8;
    const __nv_bfloat16* srcB1 = Bgl + (size_t)(n0 + r) * K + hf*8;
    uint32_t sbase = (uint32_t)__cvta_generic_to_shared(smem);
    uint32_t doff = r*48 + hf*16;

    int NK = K >> 4;

    #define PF(st, kc) { \
        uint32_t b_ = sbase + (st)*ST_B + doff; \
        cp16(b_,            srcA0 + (kc)); \
        cp16(b_ +   PL_B,   srcA1 + (kc)); \
        cp16(b_ + 2*PL_B,   srcB0 + (kc)); \
        cp16(b_ + 3*PL_B,   srcB1 + (kc)); \
        asm volatile("cp.async.commit_group;"); }

    PF(0, 0); PF(1, 16); PF(2, 32);

    int a_row = (lane & 7) + ((lane >> 3) & 1) * 8;
    int a_kb  = ((lane >> 4) & 1) * 16;
    int b_row = (lane & 7) + ((lane >> 4) & 1) * 8;
    int b_kb  = ((lane >> 3) & 1) * 16;
    uint32_t aoffA = (uint32_t)(wm*64 + a_row) * 48 + a_kb;
    uint32_t aoffB = (uint32_t)(wn*32 + b_row) * 48 + b_kb;

    int st = 0;
    for (int ks = 0; ks < NK; ks++) {
        int rem = NK - 1 - ks;
        if (rem >= 2)      asm volatile("cp.async.wait_group 2;");
        else if (rem == 1) asm volatile("cp.async.wait_group 1;");
        else               asm volatile("cp.async.wait_group 0;");
        __syncthreads();
        uint32_t base = sbase + st*ST_B;
        uint32_t bh[4][2], bl[4][2];
        #pragma unroll
        for (int jp = 0; jp < 2; jp++) {
            uint32_t ad = base + 2*PL_B + aoffB + jp*768;
            uint32_t t0[4], t1[4];
            ldsm4(t0, ad);
            ldsm4(t1, ad + PL_B);
            bh[2*jp][0]=t0[0]; bh[2*jp][1]=t0[1]; bh[2*jp+1][0]=t0[2]; bh[2*jp+1][1]=t0[3];
            bl[2*jp][0]=t1[0]; bl[2*jp][1]=t1[1]; bl[2*jp+1][0]=t1[2]; bl[2*jp+1][1]=t1[3];
        }
        #pragma unroll
        for (int i = 0; i < 4; i++) {
            uint32_t ah[4], al[4];
            uint32_t ad = base + aoffA + i*768;
            ldsm4(ah, ad);
            ldsm4(al, ad + PL_B);
            #pragma unroll
            for (int j = 0; j < 4; j++) {
                mma16816(acc[i][j], al, bh[j]);
                mma16816(acc[i][j], ah, bl[j]);
                mma16816(acc[i][j], ah, bh[j]);
            }
        }
        __syncthreads();
        if (ks + 3 < NK) PF(st, (ks+3)*16);
        st++; if (st == 3) st = 0;
    }
    #undef PF

    #pragma unroll
    for (int i = 0; i < 4; i++) {
        int r0 = m0 + wm*64 + i*16 + g;
        int r1 = r0 + 8;
        #pragma unroll
        for (int j = 0; j < 4; j++) {
            int col = n0 + wn*32 + j*8 + 2*tg;
            if (EPI == 0) {
                *(float2*)&C[(size_t)r0*N + col] = make_float2(acc[i][j][0], acc[i][j][1]);
                *(float2*)&C[(size_t)r1*N + col] = make_float2(acc[i][j][2], acc[i][j][3]);
            } else if (EPI == 1) {
                float2 c0 = *(float2*)&C[(size_t)r0*N + col];
                float2 c1 = *(float2*)&C[(size_t)r1*N + col];
                const float* g0 = aux + (size_t)(r0 >> 8) * MODW + col;
                const float* g1 = aux + (size_t)(r1 >> 8) * MODW + col;
                c0.x += acc[i][j][0] * g0[0]; c0.y += acc[i][j][1] * g0[1];
                c1.x += acc[i][j][2] * g1[0]; c1.y += acc[i][j][3] * g1[1];
                *(float2*)&C[(size_t)r0*N + col] = c0;
                *(float2*)&C[(size_t)r1*N + col] = c1;
            } else {
                const float* u0 = aux + (size_t)r0*N + col;
                const float* u1 = aux + (size_t)r1*N + col;
                float v, o0, o1, o2, o3;
                v = acc[i][j][0]; o0 = u0[0] * (v / (1.f + __expf(-v)));
                v = acc[i][j][1]; o1 = u0[1] * (v / (1.f + __expf(-v)));
                v = acc[i][j][2]; o2 = u1[0] * (v / (1.f + __expf(-v)));
                v = acc[i][j][3]; o3 = u1[1] * (v / (1.f + __expf(-v)));
                *(uint32_t*)&Oh[(size_t)r0*N + col] = pkh(o0, o1);
                *(uint32_t*)&Oh[(size_t)r1*N + col] = pkh(o2, o3);
                *(uint32_t*)&Ol[(size_t)r0*N + col] = pkl(o0, o1);
                *(uint32_t*)&Ol[(size_t)r1*N + col] = pkl(o2, o3);
            }
        }
    }
}

// ---------------- qkv split + per-head RMSNorm -> bf16 hi/lo planes [h][s][64] ----------------
__global__ void splitnorm_kernel(const float* __restrict__ sq, const float* __restrict__ sk) {
    int s = blockIdx.x, hh = blockIdx.y, d = threadIdx.x;
    const float* base = g_qkv + (size_t)s * (3*DMODEL) + hh * DHEAD;
    float qv = base[d], kv = base[DMODEL + d], vv = base[2*DMODEL + d];
    __shared__ float red[4];
    float qs = qv * qv, ks = kv * kv;
    #pragma unroll
    for (int o = 16; o > 0; o >>= 1) {
        qs += __shfl_xor_sync(0xffffffffu, qs, o);
        ks += __shfl_xor_sync(0xffffffffu, ks, o);
    }
    if ((d & 31) == 0) { red[d >> 5] = qs; red[2 + (d >> 5)] = ks; }
    __syncthreads();
    float qr = 1.f / (sqrtf((red[0]+red[1]) * (1.f/64.f)) + EPSV);
    float kr = 1.f / (sqrtf((red[2]+red[3]) * (1.f/64.f)) + EPSV);
    float qo = qv * qr * sq[d];
    float ko = kv * kr * sk[d];
    size_t o = ((size_t)hh * SDIM + s) * DHEAD + d;
    __nv_bfloat16 h;
    h = __float2bfloat16(qo); g_qph[o] = h; g_qpl[o] = __float2bfloat16(qo - __bfloat162float(h));
    h = __float2bfloat16(ko); g_kph[o] = h; g_kpl[o] = __float2bfloat16(ko - __bfloat162float(h));
    h = __float2bfloat16(vv); g_vph[o] = h; g_vpl[o] = __float2bfloat16(vv - __bfloat162float(h));
}

// ---------------- tensor-core flash attention (block-causal, unscaled) ----------------
// 128 threads / 4 warps; 64 q-rows per CTA; 64-key tiles double-buffered.
// smem stage: Kh(0) Kl(9216) Vh(18432) Vl(27648); stage size 36864B.
#define FROW 144      // bytes per smem row (64 bf16 data + 8 pad)
#define FPL  9216     // plane bytes (64*144)
#define FSTG 36864

__global__ void __launch_bounds__(128) flash_tc() {
    extern __shared__ __align__(16) char fsm[];
    int tid = threadIdx.x, lane = tid & 31, w = tid >> 5;
    int qb = blockIdx.x, hh = blockIdx.y;
    int q0 = qb * 64;
    int nk = ((qb >> 2) + 1) * 4;
    int g = lane >> 2, tg = lane & 3;
    uint32_t sb = (uint32_t)__cvta_generic_to_shared(fsm);
    size_t hbase = (size_t)hh * SDIM;

    // ---- load Q planes into stage0, ldmatrix to regs ----
    #pragma unroll
    for (int i = 0; i < 4; i++) {
        int ch = i*128 + tid, r = ch >> 3, hf = ch & 7;
        cp16(sb + r*FROW + hf*16,       g_qph + (hbase + q0 + r)*DHEAD + hf*8);
        cp16(sb + FPL + r*FROW + hf*16, g_qpl + (hbase + q0 + r)*DHEAD + hf*8);
    }
    asm volatile("cp.async.commit_group;");
    asm volatile("cp.async.wait_group 0;");
    __syncthreads();

    int a_row = (lane & 7) + ((lane >> 3) & 1) * 8;
    int a_kb  = ((lane >> 4) & 1) * 16;
    uint32_t qh[4][4], ql[4][4];
    {
        uint32_t qoff = sb + (uint32_t)(w*16 + a_row)*FROW + a_kb;
        #pragma unroll
        for (int kb = 0; kb < 4; kb++) {
            ldsm4(qh[kb], qoff + kb*32);
            ldsm4(ql[kb], qoff + FPL + kb*32);
        }
    }
    __syncthreads();

    // ---- prefetch K/V tiles 0,1 ----
    #define FPF(t, buf) { \
        uint32_t bb = sb + (buf)*FSTG; \
        size_t gsrc = (hbase + (t)*64) * DHEAD; \
        _Pragma("unroll") \
        for (int i = 0; i < 4; i++) { \
            int ch = i*128 + tid, r = ch >> 3, hf = ch & 7; \
            uint32_t so = r*FROW + hf*16; size_t go = gsrc + r*DHEAD + hf*8; \
            cp16(bb + so,         g_kph + go); \
            cp16(bb + FPL + so,   g_kpl + go); \
            cp16(bb + 2*FPL + so, g_vph + go); \
            cp16(bb + 3*FPL + so, g_vpl + go); \
        } \
        asm volatile("cp.async.commit_group;"); }

    FPF(0, 0); FPF(1, 1);

    int b_row = (lane & 7) + ((lane >> 4) & 1) * 8;
    int b_kb  = ((lane >> 3) & 1) * 16;
    int v_srow = (lane & 7) + ((lane >> 3) & 1) * 8;
    int v_dcol = ((lane >> 4) & 1) * 8;

    float O[8][4];
    #pragma unroll
    for (int j = 0; j < 8; j++)
        #pragma unroll
        for (int c = 0; c < 4; c++) O[j][c] = 0.f;
    float mm0 = -1e30f, mm1 = -1e30f, ll0 = 0.f, ll1 = 0.f;

    for (int t = 0; t < nk; t++) {
        if (t + 1 < nk) asm volatile("cp.async.wait_group 1;");
        else            asm volatile("cp.async.wait_group 0;");
        __syncthreads();
        uint32_t bb = sb + (t & 1)*FSTG;

        // ---- S = Q K^T (3-term) ----
        float S[8][4];
        #pragma unroll
        for (int j = 0; j < 8; j++)
            #pragma unroll
            for (int c = 0; c < 4; c++) S[j][c] = 0.f;
        #pragma unroll
        for (int jp = 0; jp < 4; jp++) {
            #pragma unroll
            for (int kb = 0; kb < 4; kb++) {
                uint32_t kh[4], kl[4];
                uint32_t ad = bb + (uint32_t)(jp*16 + b_row)*FROW + b_kb + kb*32;
                ldsm4(kh, ad);
                ldsm4(kl, ad + FPL);
                mma16816(S[2*jp],   ql[kb], &kh[0]);
                mma16816(S[2*jp],   qh[kb], &kl[0]);
                mma16816(S[2*jp],   qh[kb], &kh[0]);
                mma16816(S[2*jp+1], ql[kb], &kh[2]);
                mma16816(S[2*jp+1], qh[kb], &kl[2]);
                mma16816(S[2*jp+1], qh[kb], &kh[2]);
            }
        }

        // ---- online softmax (rows g, g+8; quad lanes share a row) ----
        float mx0 = -1e30f, mx1 = -1e30f;
        #pragma unroll
        for (int j = 0; j < 8; j++) {
            mx0 = fmaxf(mx0, fmaxf(S[j][0], S[j][1]));
            mx1 = fmaxf(mx1, fmaxf(S[j][2], S[j][3]));
        }
        #pragma unroll
        for (int o = 1; o < 4; o <<= 1) {
            mx0 = fmaxf(mx0, __shfl_xor_sync(0xffffffffu, mx0, o));
            mx1 = fmaxf(mx1, __shfl_xor_sync(0xffffffffu, mx1, o));
        }
        float mn0 = fmaxf(mm0, mx0), mn1 = fmaxf(mm1, mx1);
        float sc0 = __expf(mm0 - mn0), sc1 = __expf(mm1 - mn1);
        mm0 = mn0; mm1 = mn1;
        float rs0 = 0.f, rs1 = 0.f;
        #pragma unroll
        for (int j = 0; j < 8; j++) {
            S[j][0] = __expf(S[j][0] - mn0); rs0 += S[j][0];
            S[j][1] = __expf(S[j][1] - mn0); rs0 += S[j][1];
            S[j][2] = __expf(S[j][2] - mn1); rs1 += S[j][2];
            S[j][3] = __expf(S[j][3] - mn1); rs1 += S[j][3];
        }
        #pragma unroll
        for (int o = 1; o < 4; o <<= 1) {
            rs0 += __shfl_xor_sync(0xffffffffu, rs0, o);
            rs1 += __shfl_xor_sync(0xffffffffu, rs1, o);
        }
        ll0 = ll0 * sc0 + rs0;
        ll1 = ll1 * sc1 + rs1;
        #pragma unroll
        for (int j = 0; j < 8; j++) {
            O[j][0] *= sc0; O[j][1] *= sc0;
            O[j][2] *= sc1; O[j][3] *= sc1;
        }

        // ---- P fragments (hi/lo) from S acc frags ----
        uint32_t ph[4][4], pl[4][4];
        #pragma unroll
        for (int kb = 0; kb < 4; kb++) {
            ph[kb][0] = pkh(S[2*kb][0],   S[2*kb][1]);
            ph[kb][1] = pkh(S[2*kb][2],   S[2*kb][3]);
            ph[kb][2] = pkh(S[2*kb+1][0], S[2*kb+1][1]);
            ph[kb][3] = pkh(S[2*kb+1][2], S[2*kb+1][3]);
            pl[kb][0] = pkl(S[2*kb][0],   S[2*kb][1]);
            pl[kb][1] = pkl(S[2*kb][2],   S[2*kb][3]);
            pl[kb][2] = pkl(S[2*kb+1][0], S[2*kb+1][1]);
            pl[kb][3] = pkl(S[2*kb+1][2], S[2*kb+1][3]);
        }

        // ---- O += P V (3-term; V^T frags via ldmatrix.trans) ----
        #pragma unroll
        for (int jp = 0; jp < 4; jp++) {
            #pragma unroll
            for (int kb = 0; kb < 4; kb++) {
                uint32_t vh[4], vl[4];
                uint32_t ad = bb + 2*FPL + (uint32_t)(kb*16 + v_srow)*FROW + (uint32_t)(jp*16 + v_dcol)*2;
                ldsm4t(vh, ad);
                ldsm4t(vl, ad + FPL);
                mma16816(O[2*jp],   pl[kb], &vh[0]);
                mma16816(O[2*jp],   ph[kb], &vl[0]);
                mma16816(O[2*jp],   ph[kb], &vh[0]);
                mma16816(O[2*jp+1], pl[kb], &vh[2]);
                mma16816(O[2*jp+1], ph[kb], &vl[2]);
                mma16816(O[2*jp+1], ph[kb], &vh[2]);
            }
        }
        __syncthreads();
        if (t + 2 < nk) FPF(t + 2, t & 1);
    }
    #undef FPF

    // ---- normalize + write z planes ----
    float inv0 = 1.f / ll0, inv1 = 1.f / ll1;
    int row0 = q0 + w*16 + g, row1 = row0 + 8;
    #pragma unroll
    for (int jd = 0; jd < 8; jd++) {
        int col = hh*DHEAD + jd*8 + 2*tg;
        float o0 = O[jd][0]*inv0, o1 = O[jd][1]*inv0;
        float o2 = O[jd][2]*inv1, o3 = O[jd][3]*inv1;
        *(uint32_t*)&g_zh[(size_t)row0*DMODEL + col] = pkh(o0, o1);
        *(uint32_t*)&g_zh[(size_t)row1*DMODEL + col] = pkh(o2, o3);
        *(uint32_t*)&g_zl[(size_t)row0*DMODEL + col] = pkl(o0, o1);
        *(uint32_t*)&g_zl[(size_t)row1*DMODEL + col] = pkl(o2, o3);
    }
}

// ---------------- output projection + unpatchify ----------------
__global__ void outproj_kernel(const float* __restrict__ Wout, const float* __restrict__ bout,
                               float* __restrict__ out) {
    __shared__ float row[DMODEL];
    int s = blockIdx.x, tid = threadIdx.x;
    for (int i = tid; i < DMODEL; i += 64) row[i] = g_h[(size_t)s * DMODEL + i];
    __syncthreads();
    if (tid < 48) {
        float acc = bout[tid];
        for (int k = 0; k < DMODEL; k++) acc += row[k] * Wout[k*48 + tid];
        int t = s >> 8, p = s & 255, oy = p >> 4, ox = p & 15;
        int c = tid >> 4, pi = (tid >> 2) & 3, pj = tid & 3;
        out[((t*3 + c)*64 + oy*4 + pi)*64 + ox*4 + pj] = acc;
    }
}

// ---------------- host ----------------
#define GEMM_SMEM (3*ST_B)
#define FLASH_SMEM (2*FSTG)

extern "C" void kernel_launch(void* const* d_in, const int* in_sizes, int n_in,
                              void* d_out, int out_size) {
    const float* x      = (const float*)d_in[0];
    const int*   actions= (const int*)  d_in[1];
    const float* ts     = (const float*)d_in[2];
    const float* conv_w = (const float*)d_in[3];
    const float* conv_b = (const float*)d_in[4];
    const float* pe     = (const float*)d_in[5];
    const float* ae     = (const float*)d_in[6];
    const float* Wmod   = (const float*)d_in[7];
    const float* bmod   = (const float*)d_in[8];
    const float* s1     = (const float*)d_in[9];
    const float* Wqkv   = (const float*)d_in[10];
    const float* Wo     = (const float*)d_in[11];
    const float* sq     = (const float*)d_in[12];
    const float* sk     = (const float*)d_in[13];
    const float* s2     = (const float*)d_in[14];
    const float* Wup    = (const float*)d_in[15];
    const float* Wgate  = (const float*)d_in[16];
    const float* Wdown  = (const float*)d_in[17];
    const float* s_final= (const float*)d_in[18];
    const float* Wmf    = (const float*)d_in[19];
    const float* bmf    = (const float*)d_in[20];
    const float* Wout   = (const float*)d_in[21];
    const float* bout   = (const float*)d_in[22];
    float* out = (float*)d_out;

    float *p_tokens, *p_cond, *p_mod, *p_h, *p_qkv, *p_u, *p_mf;
    __nv_bfloat16 *p_whi, *p_wlo, *p_hh, *p_hl, *p_zh, *p_zl, *p_acth, *p_actl;
    cudaGetSymbolAddress((void**)&p_tokens, g_tokens);
    cudaGetSymbolAddress((void**)&p_cond,   g_cond);
    cudaGetSymbolAddress((void**)&p_mod,    g_mod);
    cudaGetSymbolAddress((void**)&p_h,      g_h);
    cudaGetSymbolAddress((void**)&p_qkv,    g_qkv);
    cudaGetSymbolAddress((void**)&p_u,      g_u);
    cudaGetSymbolAddress((void**)&p_mf,     g_mf);
    cudaGetSymbolAddress((void**)&p_whi,    g_whi);
    cudaGetSymbolAddress((void**)&p_wlo,    g_wlo);
    cudaGetSymbolAddress((void**)&p_hh,     g_hh);
    cudaGetSymbolAddress((void**)&p_hl,     g_hl);
    cudaGetSymbolAddress((void**)&p_zh,     g_zh);
    cudaGetSymbolAddress((void**)&p_zl,     g_zl);
    cudaGetSymbolAddress((void**)&p_acth,   g_acth);
    cudaGetSymbolAddress((void**)&p_actl,   g_actl);

    cudaFuncSetAttribute(flash_tc, cudaFuncAttributeMaxDynamicSharedMemorySize, FLASH_SMEM);
    cudaFuncSetAttribute(gemm_bf16<0>, cudaFuncAttributeMaxDynamicSharedMemorySize, GEMM_SMEM);
    cudaFuncSetAttribute(gemm_bf16<1>, cudaFuncAttributeMaxDynamicSharedMemorySize, GEMM_SMEM);
    cudaFuncSetAttribute(gemm_bf16<2>, cudaFuncAttributeMaxDynamicSharedMemorySize, GEMM_SMEM);

    // ---- weight transpose + split ----
    dim3 tb(32, 8);
    for (int l = 0; l < NLAYER; l++) {
        size_t lb = (size_t)l * LWSTRIDE;
        wsplit_kernel<<<dim3(2304/32, 768/32), tb>>>(Wqkv  + (size_t)l*DMODEL*3*DMODEL, p_whi + lb + OFF_QKV,  p_wlo + lb + OFF_QKV,  768, 2304);
        wsplit_kernel<<<dim3( 768/32, 768/32), tb>>>(Wo    + (size_t)l*DMODEL*DMODEL,   p_whi + lb + OFF_WO,   p_wlo + lb + OFF_WO,   768,  768);
        wsplit_kernel<<<dim3(3072/32, 768/32), tb>>>(Wup   + (size_t)l*DMODEL*EXPD,     p_whi + lb + OFF_UP,   p_wlo + lb + OFF_UP,   768, 3072);
        wsplit_kernel<<<dim3(3072/32, 768/32), tb>>>(Wgate + (size_t)l*DMODEL*EXPD,     p_whi + lb + OFF_GATE, p_wlo + lb + OFF_GATE, 768, 3072);
        wsplit_kernel<<<dim3( 768/32, 3072/32), tb>>>(Wdown + (size_t)l*EXPD*DMODEL,    p_whi + lb + OFF_DOWN, p_wlo + lb + OFF_DOWN, 3072, 768);
    }

    patchify_kernel<<<SDIM, 256>>>(x, conv_w, conv_b, pe);
    cond_kernel<<<TFRM, 256>>>(actions, ts, ae);

    for (int l = 0; l < NLAYER; l++) {
        size_t lb = (size_t)l * LWSTRIDE;
        const float* bm  = bmod  + (size_t)l * MODW;
        const float* s1l = s1    + (size_t)l * DMODEL;
        const float* sql = sq    + (size_t)l * DHEAD;
        const float* skl = sk    + (size_t)l * DHEAD;
        const float* s2l = s2    + (size_t)l * DMODEL;

        smallm_gemm<<<MODW/128, 256>>>(p_cond, Wmod + (size_t)l*DMODEL*MODW, bm, p_mod, MODW);
        modulate_kernel<<<SDIM, 256>>>(p_tokens, p_h, s1l, p_mod, MODW, 0, 768);
        gemm_bf16<0><<<dim3(2304/128, SDIM/128), 256, GEMM_SMEM>>>(
            p_hh, p_hl, p_whi + lb + OFF_QKV, p_wlo + lb + OFF_QKV,
            p_qkv, SDIM, 2304, 768, nullptr, nullptr, nullptr);
        splitnorm_kernel<<<dim3(SDIM, NHEAD), 64>>>(sql, skl);
        flash_tc<<<dim3(SDIM/64, NHEAD), 128, FLASH_SMEM>>>();
        gemm_bf16<1><<<dim3(768/128, SDIM/128), 256, GEMM_SMEM>>>(
            p_zh, p_zl, p_whi + lb + OFF_WO, p_wlo + lb + OFF_WO,
            p_tokens, SDIM, 768, 768, p_mod + 1536, nullptr, nullptr);
        modulate_kernel<<<SDIM, 256>>>(p_tokens, p_h, s2l, p_mod, MODW, 2304, 3072);
        gemm_bf16<0><<<dim3(3072/128, SDIM/128), 256, GEMM_SMEM>>>(
            p_hh, p_hl, p_whi + lb + OFF_UP, p_wlo + lb + OFF_UP,
            p_u, SDIM, 3072, 768, nullptr, nullptr, nullptr);
        gemm_bf16<2><<<dim3(3072/128, SDIM/128), 256, GEMM_SMEM>>>(
            p_hh, p_hl, p_whi + lb + OFF_GATE, p_wlo + lb + OFF_GATE,
            nullptr, SDIM, 3072, 768, p_u, p_acth, p_actl);
        gemm_bf16<1><<<dim3(768/128, SDIM/128), 256, GEMM_SMEM>>>(
            p_acth, p_actl, p_whi + lb + OFF_DOWN, p_wlo + lb + OFF_DOWN,
            p_tokens, SDIM, 768, 3072, p_mod + 3840, nullptr, nullptr);
    }

    smallm_gemm<<<2*DMODEL/128, 256>>>(p_cond, Wmf, bmf, p_mf, 2*DMODEL);
    modulate_kernel<<<SDIM, 256>>>(p_tokens, p_h, s_final, p_mf, 2*DMODEL, 0, 768);
    outproj_kernel<<<SDIM, 64>>>(Wout, bout, out);
}

// round 10
// speedup vs baseline: 2.6485x; 1.1446x over previous
#include <cuda_runtime.h>
#include <cuda_bf16.h>
#include <math.h>
#include <stdint.h>

// ---------------- constants ----------------
#define DMODEL 768
#define NHEAD  12
#define DHEAD  64
#define NLAYER 4
#define PPF    256
#define SDIM   2048   // TF * PPF
#define TFRM   8
#define EXPD   3072   // EXP * D
#define MODW   4608   // 6*D
#define EPSV   1e-6f

// weight plane layout (transposed [N][K] bf16), per-layer stride and offsets
#define LWSTRIDE 9437184
#define OFF_QKV  0
#define OFF_WO   1769472
#define OFF_UP   2359296
#define OFF_GATE 4718592
#define OFF_DOWN 7077888

// ---------------- scratch ----------------
__device__ float g_tokens[SDIM*DMODEL];
__device__ float g_cond[TFRM*DMODEL];
__device__ float g_mod[TFRM*MODW];
__device__ float g_h[SDIM*DMODEL];
__device__ float g_qkv[SDIM*3*DMODEL];
__device__ float g_u[SDIM*EXPD];        // also reused as split-K partial buffer (2 x 2048 x 768)
__device__ float g_mf[TFRM*2*DMODEL];

__device__ __nv_bfloat16 g_whi[4*LWSTRIDE];
__device__ __nv_bfloat16 g_wlo[4*LWSTRIDE];
__device__ __nv_bfloat16 g_hh[SDIM*DMODEL],  g_hl[SDIM*DMODEL];
__device__ __nv_bfloat16 g_zh[SDIM*DMODEL],  g_zl[SDIM*DMODEL];
__device__ __nv_bfloat16 g_acth[SDIM*EXPD],  g_actl[SDIM*EXPD];
// attention planes [h][s][64]
__device__ __nv_bfloat16 g_qph[NHEAD*SDIM*DHEAD], g_qpl[NHEAD*SDIM*DHEAD];
__device__ __nv_bfloat16 g_kph[NHEAD*SDIM*DHEAD], g_kpl[NHEAD*SDIM*DHEAD];
__device__ __nv_bfloat16 g_vph[NHEAD*SDIM*DHEAD], g_vpl[NHEAD*SDIM*DHEAD];

// ---------------- helpers ----------------
__device__ __forceinline__ void cp16(uint32_t d, const void* s) {
    asm volatile("cp.async.cg.shared.global [%0], [%1], 16;" :: "r"(d), "l"(s));
}
__device__ __forceinline__ void ldsm4(uint32_t* r, uint32_t a) {
    asm volatile("ldmatrix.sync.aligned.m8n8.x4.shared.b16 {%0,%1,%2,%3}, [%4];"
                 : "=r"(r[0]), "=r"(r[1]), "=r"(r[2]), "=r"(r[3]) : "r"(a));
}
__device__ __forceinline__ void ldsm4t(uint32_t* r, uint32_t a) {
    asm volatile("ldmatrix.sync.aligned.m8n8.x4.trans.shared.b16 {%0,%1,%2,%3}, [%4];"
                 : "=r"(r[0]), "=r"(r[1]), "=r"(r[2]), "=r"(r[3]) : "r"(a));
}
__device__ __forceinline__ void mma16816(float* d, const uint32_t* a, const uint32_t* b) {
    asm volatile("mma.sync.aligned.m16n8k16.row.col.f32.bf16.bf16.f32 "
        "{%0,%1,%2,%3}, {%4,%5,%6,%7}, {%8,%9}, {%0,%1,%2,%3};"
        : "+f"(d[0]), "+f"(d[1]), "+f"(d[2]), "+f"(d[3])
        : "r"(a[0]), "r"(a[1]), "r"(a[2]), "r"(a[3]), "r"(b[0]), "r"(b[1]));
}
__device__ __forceinline__ uint32_t pkh(float a, float b) {
    __nv_bfloat162 t; t.x = __float2bfloat16(a); t.y = __float2bfloat16(b);
    return *(uint32_t*)&t;
}
__device__ __forceinline__ uint32_t pkl(float a, float b) {
    float ra = a - __bfloat162float(__float2bfloat16(a));
    float rb = b - __bfloat162float(__float2bfloat16(b));
    return pkh(ra, rb);
}

// ---------------- weight transpose + bf16 hi/lo split (batched over layers via z) ----------------
__global__ void wsplit_kernel(const float* __restrict__ W, __nv_bfloat16* __restrict__ oh,
                              __nv_bfloat16* __restrict__ ol, int K, int N) {
    int l = blockIdx.z;
    W  += (size_t)l * K * N;
    oh += (size_t)l * LWSTRIDE;
    ol += (size_t)l * LWSTRIDE;
    __shared__ float t[32][33];
    int n0 = blockIdx.x*32, k0 = blockIdx.y*32;
    int tx = threadIdx.x, ty = threadIdx.y;
    #pragma unroll
    for (int r = ty; r < 32; r += 8) t[r][tx] = W[(size_t)(k0+r)*N + n0+tx];
    __syncthreads();
    #pragma unroll
    for (int r = ty; r < 32; r += 8) {
        float v = t[tx][r];
        __nv_bfloat16 h = __float2bfloat16(v);
        size_t o = (size_t)(n0+r)*K + k0+tx;
        oh[o] = h; ol[o] = __float2bfloat16(v - __bfloat162float(h));
    }
}

// ---------------- patchify ----------------
__global__ void patchify_kernel(const float* __restrict__ x, const float* __restrict__ cw,
                                const float* __restrict__ cb, const float* __restrict__ pe) {
    int s = blockIdx.x;
    int t = s >> 8, p = s & 255, oy = p >> 4, ox = p & 15;
    __shared__ float patch[75];
    int tid = threadIdx.x;
    if (tid < 75) {
        int c = tid / 25, rem = tid % 25, r = rem / 5, w = rem % 5;
        int iy = oy*4 - 2 + r, ix = ox*4 - 2 + w;
        float v = 0.f;
        if (iy >= 0 && iy < 64 && ix >= 0 && ix < 64)
            v = x[((t*3 + c)*64 + iy)*64 + ix];
        patch[tid] = v;
    }
    __syncthreads();
    for (int d = tid; d < DMODEL; d += 256) {
        float acc = cb[d];
        const float* w = cw + d*75;
        #pragma unroll
        for (int i = 0; i < 75; i++) acc += patch[i] * w[i];
        g_tokens[s*DMODEL + d] = acc + pe[p*DMODEL + d];
    }
}

// ---------------- conditioning ----------------
__global__ void cond_kernel(const int* __restrict__ actions, const float* __restrict__ ts,
                            const float* __restrict__ ae) {
    int f = blockIdx.x;
    int a = actions[f];
    float tsv = ts[f];
    int ti = (int)(tsv * 1000.0f);
    if (ti > 999) ti = 999;
    float tif = (float)ti;
    for (int d = threadIdx.x; d < DMODEL; d += blockDim.x) {
        int j = (d < 384) ? d : d - 384;
        float th = powf(500.0f, -((float)j) / 384.0f);
        float ang = tif * th;
        float te = (d < 384) ? sinf(ang) : cosf(ang);
        float c = te + ae[a*DMODEL + d];
        g_cond[f*DMODEL + d] = c / (1.f + expf(-c));
    }
}

// ---------------- small-M GEMM ----------------
__global__ void smallm_gemm(const float* __restrict__ A, const float* __restrict__ B,
                            const float* __restrict__ bias, float* __restrict__ C, int N) {
    __shared__ float As[8*DMODEL];
    int tid = threadIdx.x;
    for (int i = tid; i < 8*DMODEL; i += 256) As[i] = A[i];
    __syncthreads();
    int col = tid & 127, rg = tid >> 7;
    int n = blockIdx.x * 128 + col;
    float acc0 = 0, acc1 = 0, acc2 = 0, acc3 = 0;
    int rb = rg * 4;
    for (int k = 0; k < DMODEL; k++) {
        float bv = B[(size_t)k * N + n];
        acc0 += As[(rb+0)*DMODEL + k] * bv;
        acc1 += As[(rb+1)*DMODEL + k] * bv;
        acc2 += As[(rb+2)*DMODEL + k] * bv;
        acc3 += As[(rb+3)*DMODEL + k] * bv;
    }
    float bs = bias[n];
    C[(rb+0)*N + n] = acc0 + bs;
    C[(rb+1)*N + n] = acc1 + bs;
    C[(rb+2)*N + n] = acc2 + bs;
    C[(rb+3)*N + n] = acc3 + bs;
}

// ---------------- RMSNorm + AdaLN modulate (fp32 + bf16 hi/lo planes) ----------------
__global__ void modulate_kernel(const float* __restrict__ in, float* __restrict__ out,
                                const float* __restrict__ sa, const float* __restrict__ mod,
                                int mstride, int off_sc, int off_b) {
    int s = blockIdx.x, tid = threadIdx.x, f = s >> 8;
    const float* row = in + (size_t)s * DMODEL;
    float v0 = row[tid], v1 = row[tid+256], v2 = row[tid+512];
    float ss = v0*v0 + v1*v1 + v2*v2;
    __shared__ float red[8];
    #pragma unroll
    for (int o = 16; o > 0; o >>= 1) ss += __shfl_xor_sync(0xffffffffu, ss, o);
    if ((tid & 31) == 0) red[tid >> 5] = ss;
    __syncthreads();
    float tot = 0.f;
    #pragma unroll
    for (int w = 0; w < 8; w++) tot += red[w];
    float rinv = 1.f / (sqrtf(tot * (1.f/768.f)) + EPSV);
    const float* mrow = mod + f * mstride;
    float* orow = out + (size_t)s * DMODEL;
    size_t base = (size_t)s * DMODEL;
    #pragma unroll
    for (int c = 0; c < 3; c++) {
        int d = tid + c*256;
        float v = (c == 0) ? v0 : (c == 1 ? v1 : v2);
        float o = v * rinv * sa[d] * (1.f + mrow[off_sc + d]) + mrow[off_b + d];
        orow[d] = o;
        __nv_bfloat16 h = __float2bfloat16(o);
        g_hh[base + d] = h;
        g_hl[base + d] = __float2bfloat16(o - __bfloat162float(h));
    }
}

// ---------------- split-K combine: tokens += (P0+P1) * gate ----------------
__global__ void combineK(const float* __restrict__ P, float* __restrict__ tokens,
                         const float* __restrict__ mod, int off_g) {
    int idx = (blockIdx.x*256 + threadIdx.x) * 4;   // over 2048*768
    int m = idx / DMODEL, n = idx % DMODEL;
    float4 a = *(const float4*)&P[idx];
    float4 b = *(const float4*)&P[idx + SDIM*DMODEL];
    const float* g = mod + (m >> 8)*MODW + off_g + n;
    float4 t = *(float4*)&tokens[idx];
    t.x += (a.x + b.x) * g[0];
    t.y += (a.y + b.y) * g[1];
    t.z += (a.z + b.z) * g[2];
    t.w += (a.w + b.w) * g[3];
    *(float4*)&tokens[idx] = t;
}

// ---------------- bf16 3-term split tensor-core GEMM ----------------
// Distance-2 prefetch, 3 stages, SINGLE sync per k16 (written stage = last iter's read stage).
// blockIdx.z = split-K slice (A/B offset kz*K along k; C offset kz*M*N). ld = full row stride.
#define KROW 24
#define PL_B  6144
#define ST_B  24576

template<int EPI>
__global__ void __launch_bounds__(256) gemm_bf16(
    const __nv_bfloat16* __restrict__ Agh, const __nv_bfloat16* __restrict__ Agl,
    const __nv_bfloat16* __restrict__ Bgh, const __nv_bfloat16* __restrict__ Bgl,
    float* __restrict__ C, int M, int N, int K, int ld,
    const float* __restrict__ aux,
    __nv_bfloat16* __restrict__ Oh, __nv_bfloat16* __restrict__ Ol)
{
    extern __shared__ __align__(16) __nv_bfloat16 smem[];
    int tid = threadIdx.x, lane = tid & 31, wid = tid >> 5;
    int m0 = blockIdx.y * 128, n0 = blockIdx.x * 128;
    int kz = blockIdx.z;
    int wm = wid >> 2, wn = wid & 3, g = lane >> 2, tg = lane & 3;

    float acc[4][4][4];
    #pragma unroll
    for (int i = 0; i < 4; i++)
        #pragma unroll
        for (int j = 0; j < 4; j++)
            #pragma unroll
            for (int c = 0; c < 4; c++) acc[i][j][c] = 0.f;

    int r = tid >> 1, hf = tid & 1;
    size_t kbase = (size_t)kz * K + hf*8;
    const __nv_bfloat16* srcA0 = Agh + (size_t)(m0 + r) * ld + kbase;
    const __nv_bfloat16* srcA1 = Agl + (size_t)(m0 + r) * ld + kbase;
    const __nv_bfloat16* srcB0 = Bgh + (size_t)(n0 + r) * ld + kbase;
    const __nv_bfloat16* srcB1 = Bgl + (size_t)(n0 + r) * ld + kbase;
    uint32_t sbase = (uint32_t)__cvta_generic_to_shared(smem);
    uint32_t doff = r*48 + hf*16;

    int NK = K >> 4;

    #define PF(st, kc) { \
        uint32_t b_ = sbase + (st)*ST_B + doff; \
        cp16(b_,            srcA0 + (kc)); \
        cp16(b_ +   PL_B,   srcA1 + (kc)); \
        cp16(b_ + 2*PL_B,   srcB0 + (kc)); \
        cp16(b_ + 3*PL_B,   srcB1 + (kc)); \
        asm volatile("cp.async.commit_group;"); }

    PF(0, 0); PF(1, 16);

    int a_row = (lane & 7) + ((lane >> 3) & 1) * 8;
    int a_kb  = ((lane >> 4) & 1) * 16;
    int b_row = (lane & 7) + ((lane >> 4) & 1) * 8;
    int b_kb  = ((lane >> 3) & 1) * 16;
    uint32_t aoffA = (uint32_t)(wm*64 + a_row) * 48 + a_kb;
    uint32_t aoffB = (uint32_t)(wn*32 + b_row) * 48 + b_kb;

    int st = 0;
    for (int ks = 0; ks < NK; ks++) {
        if (ks + 1 < NK) asm volatile("cp.async.wait_group 1;");
        else             asm volatile("cp.async.wait_group 0;");
        __syncthreads();
        uint32_t base = sbase + st*ST_B;
        uint32_t bh[4][2], bl[4][2];
        #pragma unroll
        for (int jp = 0; jp < 2; jp++) {
            uint32_t ad = base + 2*PL_B + aoffB + jp*768;
            uint32_t t0[4], t1[4];
            ldsm4(t0, ad);
            ldsm4(t1, ad + PL_B);
            bh[2*jp][0]=t0[0]; bh[2*jp][1]=t0[1]; bh[2*jp+1][0]=t0[2]; bh[2*jp+1][1]=t0[3];
            bl[2*jp][0]=t1[0]; bl[2*jp][1]=t1[1]; bl[2*jp+1][0]=t1[2]; bl[2*jp+1][1]=t1[3];
        }
        #pragma unroll
        for (int i = 0; i < 4; i++) {
            uint32_t ah[4], al[4];
            uint32_t ad = base + aoffA + i*768;
            ldsm4(ah, ad);
            ldsm4(al, ad + PL_B);
            #pragma unroll
            for (int j = 0; j < 4; j++) {
                mma16816(acc[i][j], al, bh[j]);
                mma16816(acc[i][j], ah, bl[j]);
                mma16816(acc[i][j], ah, bh[j]);
            }
        }
        // prefetch into stage (st+2)%3 = the stage consumed LAST iteration;
        // every warp passed this iteration's barrier, so its reads are done.
        if (ks + 2 < NK) {
            int wst = st + 2; if (wst >= 3) wst -= 3;
            PF(wst, (ks+2)*16);
        }
        st++; if (st == 3) st = 0;
    }
    #undef PF

    C += (size_t)kz * M * N;
    #pragma unroll
    for (int i = 0; i < 4; i++) {
        int r0 = m0 + wm*64 + i*16 + g;
        int r1 = r0 + 8;
        #pragma unroll
        for (int j = 0; j < 4; j++) {
            int col = n0 + wn*32 + j*8 + 2*tg;
            if (EPI == 0) {
                *(float2*)&C[(size_t)r0*N + col] = make_float2(acc[i][j][0], acc[i][j][1]);
                *(float2*)&C[(size_t)r1*N + col] = make_float2(acc[i][j][2], acc[i][j][3]);
            } else if (EPI == 1) {
                float2 c0 = *(float2*)&C[(size_t)r0*N + col];
                float2 c1 = *(float2*)&C[(size_t)r1*N + col];
                const float* g0 = aux + (size_t)(r0 >> 8) * MODW + col;
                const float* g1 = aux + (size_t)(r1 >> 8) * MODW + col;
                c0.x += acc[i][j][0] * g0[0]; c0.y += acc[i][j][1] * g0[1];
                c1.x += acc[i][j][2] * g1[0]; c1.y += acc[i][j][3] * g1[1];
                *(float2*)&C[(size_t)r0*N + col] = c0;
                *(float2*)&C[(size_t)r1*N + col] = c1;
            } else {
                const float* u0 = aux + (size_t)r0*N + col;
                const float* u1 = aux + (size_t)r1*N + col;
                float v, o0, o1, o2, o3;
                v = acc[i][j][0]; o0 = u0[0] * (v / (1.f + __expf(-v)));
                v = acc[i][j][1]; o1 = u0[1] * (v / (1.f + __expf(-v)));
                v = acc[i][j][2]; o2 = u1[0] * (v / (1.f + __expf(-v)));
                v = acc[i][j][3]; o3 = u1[1] * (v / (1.f + __expf(-v)));
                *(uint32_t*)&Oh[(size_t)r0*N + col] = pkh(o0, o1);
                *(uint32_t*)&Oh[(size_t)r1*N + col] = pkh(o2, o3);
                *(uint32_t*)&Ol[(size_t)r0*N + col] = pkl(o0, o1);
                *(uint32_t*)&Ol[(size_t)r1*N + col] = pkl(o2, o3);
            }
        }
    }
}

// ---------------- qkv split + per-head RMSNorm -> bf16 hi/lo planes [h][s][64] ----------------
__global__ void splitnorm_kernel(const float* __restrict__ sq, const float* __restrict__ sk) {
    int s = blockIdx.x, hh = blockIdx.y, d = threadIdx.x;
    const float* base = g_qkv + (size_t)s * (3*DMODEL) + hh * DHEAD;
    float qv = base[d], kv = base[DMODEL + d], vv = base[2*DMODEL + d];
    __shared__ float red[4];
    float qs = qv * qv, ks = kv * kv;
    #pragma unroll
    for (int o = 16; o > 0; o >>= 1) {
        qs += __shfl_xor_sync(0xffffffffu, qs, o);
        ks += __shfl_xor_sync(0xffffffffu, ks, o);
    }
    if ((d & 31) == 0) { red[d >> 5] = qs; red[2 + (d >> 5)] = ks; }
    __syncthreads();
    float qr = 1.f / (sqrtf((red[0]+red[1]) * (1.f/64.f)) + EPSV);
    float kr = 1.f / (sqrtf((red[2]+red[3]) * (1.f/64.f)) + EPSV);
    float qo = qv * qr * sq[d];
    float ko = kv * kr * sk[d];
    size_t o = ((size_t)hh * SDIM + s) * DHEAD + d;
    __nv_bfloat16 h;
    h = __float2bfloat16(qo); g_qph[o] = h; g_qpl[o] = __float2bfloat16(qo - __bfloat162float(h));
    h = __float2bfloat16(ko); g_kph[o] = h; g_kpl[o] = __float2bfloat16(ko - __bfloat162float(h));
    h = __float2bfloat16(vv); g_vph[o] = h; g_vpl[o] = __float2bfloat16(vv - __bfloat162float(h));
}

// ---------------- tensor-core flash attention (block-causal, unscaled) ----------------
#define FROW 144      // bytes per smem row (64 bf16 data + 8 pad)
#define FPL  9216     // plane bytes (64*144)
#define FSTG 36864

__global__ void __launch_bounds__(128) flash_tc() {
    extern __shared__ __align__(16) char fsm[];
    int tid = threadIdx.x, lane = tid & 31, w = tid >> 5;
    int qb = blockIdx.x, hh = blockIdx.y;
    int q0 = qb * 64;
    int nk = ((qb >> 2) + 1) * 4;
    int g = lane >> 2, tg = lane & 3;
    uint32_t sb = (uint32_t)__cvta_generic_to_shared(fsm);
    size_t hbase = (size_t)hh * SDIM;

    // ---- load Q planes into stage0, ldmatrix to regs ----
    #pragma unroll
    for (int i = 0; i < 4; i++) {
        int ch = i*128 + tid, r = ch >> 3, hf = ch & 7;
        cp16(sb + r*FROW + hf*16,       g_qph + (hbase + q0 + r)*DHEAD + hf*8);
        cp16(sb + FPL + r*FROW + hf*16, g_qpl + (hbase + q0 + r)*DHEAD + hf*8);
    }
    asm volatile("cp.async.commit_group;");
    asm volatile("cp.async.wait_group 0;");
    __syncthreads();

    int a_row = (lane & 7) + ((lane >> 3) & 1) * 8;
    int a_kb  = ((lane >> 4) & 1) * 16;
    uint32_t qh[4][4], ql[4][4];
    {
        uint32_t qoff = sb + (uint32_t)(w*16 + a_row)*FROW + a_kb;
        #pragma unroll
        for (int kb = 0; kb < 4; kb++) {
            ldsm4(qh[kb], qoff + kb*32);
            ldsm4(ql[kb], qoff + FPL + kb*32);
        }
    }
    __syncthreads();

    // ---- prefetch K/V tiles 0,1 ----
    #define FPF(t, buf) { \
        uint32_t bb = sb + (buf)*FSTG; \
        size_t gsrc = (hbase + (t)*64) * DHEAD; \
        _Pragma("unroll") \
        for (int i = 0; i < 4; i++) { \
            int ch = i*128 + tid, r = ch >> 3, hf = ch & 7; \
            uint32_t so = r*FROW + hf*16; size_t go = gsrc + r*DHEAD + hf*8; \
            cp16(bb + so,         g_kph + go); \
            cp16(bb + FPL + so,   g_kpl + go); \
            cp16(bb + 2*FPL + so, g_vph + go); \
            cp16(bb + 3*FPL + so, g_vpl + go); \
        } \
        asm volatile("cp.async.commit_group;"); }

    FPF(0, 0); FPF(1, 1);

    int b_row = (lane & 7) + ((lane >> 4) & 1) * 8;
    int b_kb  = ((lane >> 3) & 1) * 16;
    int v_srow = (lane & 7) + ((lane >> 3) & 1) * 8;
    int v_dcol = ((lane >> 4) & 1) * 8;

    float O[8][4];
    #pragma unroll
    for (int j = 0; j < 8; j++)
        #pragma unroll
        for (int c = 0; c < 4; c++) O[j][c] = 0.f;
    float mm0 = -1e30f, mm1 = -1e30f, ll0 = 0.f, ll1 = 0.f;

    for (int t = 0; t < nk; t++) {
        if (t + 1 < nk) asm volatile("cp.async.wait_group 1;");
        else            asm volatile("cp.async.wait_group 0;");
        __syncthreads();
        uint32_t bb = sb + (t & 1)*FSTG;

        // ---- S = Q K^T (3-term) ----
        float S[8][4];
        #pragma unroll
        for (int j = 0; j < 8; j++)
            #pragma unroll
            for (int c = 0; c < 4; c++) S[j][c] = 0.f;
        #pragma unroll
        for (int jp = 0; jp < 4; jp++) {
            #pragma unroll
            for (int kb = 0; kb < 4; kb++) {
                uint32_t kh[4], kl[4];
                uint32_t ad = bb + (uint32_t)(jp*16 + b_row)*FROW + b_kb + kb*32;
                ldsm4(kh, ad);
                ldsm4(kl, ad + FPL);
                mma16816(S[2*jp],   ql[kb], &kh[0]);
                mma16816(S[2*jp],   qh[kb], &kl[0]);
                mma16816(S[2*jp],   qh[kb], &kh[0]);
                mma16816(S[2*jp+1], ql[kb], &kh[2]);
                mma16816(S[2*jp+1], qh[kb], &kl[2]);
                mma16816(S[2*jp+1], qh[kb], &kh[2]);
            }
        }

        // ---- online softmax ----
        float mx0 = -1e30f, mx1 = -1e30f;
        #pragma unroll
        for (int j = 0; j < 8; j++) {
            mx0 = fmaxf(mx0, fmaxf(S[j][0], S[j][1]));
            mx1 = fmaxf(mx1, fmaxf(S[j][2], S[j][3]));
        }
        #pragma unroll
        for (int o = 1; o < 4; o <<= 1) {
            mx0 = fmaxf(mx0, __shfl_xor_sync(0xffffffffu, mx0, o));
            mx1 = fmaxf(mx1, __shfl_xor_sync(0xffffffffu, mx1, o));
        }
        float mn0 = fmaxf(mm0, mx0), mn1 = fmaxf(mm1, mx1);
        float sc0 = __expf(mm0 - mn0), sc1 = __expf(mm1 - mn1);
        mm0 = mn0; mm1 = mn1;
        float rs0 = 0.f, rs1 = 0.f;
        #pragma unroll
        for (int j = 0; j < 8; j++) {
            S[j][0] = __expf(S[j][0] - mn0); rs0 += S[j][0];
            S[j][1] = __expf(S[j][1] - mn0); rs0 += S[j][1];
            S[j][2] = __expf(S[j][2] - mn1); rs1 += S[j][2];
            S[j][3] = __expf(S[j][3] - mn1); rs1 += S[j][3];
        }
        #pragma unroll
        for (int o = 1; o < 4; o <<= 1) {
            rs0 += __shfl_xor_sync(0xffffffffu, rs0, o);
            rs1 += __shfl_xor_sync(0xffffffffu, rs1, o);
        }
        ll0 = ll0 * sc0 + rs0;
        ll1 = ll1 * sc1 + rs1;
        #pragma unroll
        for (int j = 0; j < 8; j++) {
            O[j][0] *= sc0; O[j][1] *= sc0;
            O[j][2] *= sc1; O[j][3] *= sc1;
        }

        // ---- P fragments (hi/lo) ----
        uint32_t ph[4][4], pl[4][4];
        #pragma unroll
        for (int kb = 0; kb < 4; kb++) {
            ph[kb][0] = pkh(S[2*kb][0],   S[2*kb][1]);
            ph[kb][1] = pkh(S[2*kb][2],   S[2*kb][3]);
            ph[kb][2] = pkh(S[2*kb+1][0], S[2*kb+1][1]);
            ph[kb][3] = pkh(S[2*kb+1][2], S[2*kb+1][3]);
            pl[kb][0] = pkl(S[2*kb][0],   S[2*kb][1]);
            pl[kb][1] = pkl(S[2*kb][2],   S[2*kb][3]);
            pl[kb][2] = pkl(S[2*kb+1][0], S[2*kb+1][1]);
            pl[kb][3] = pkl(S[2*kb+1][2], S[2*kb+1][3]);
        }

        // ---- O += P V (3-term) ----
        #pragma unroll
        for (int jp = 0; jp < 4; jp++) {
            #pragma unroll
            for (int kb = 0; kb < 4; kb++) {
                uint32_t vh[4], vl[4];
                uint32_t ad = bb + 2*FPL + (uint32_t)(kb*16 + v_srow)*FROW + (uint32_t)(jp*16 + v_dcol)*2;
                ldsm4t(vh, ad);
                ldsm4t(vl, ad + FPL);
                mma16816(O[2*jp],   pl[kb], &vh[0]);
                mma16816(O[2*jp],   ph[kb], &vl[0]);
                mma16816(O[2*jp],   ph[kb], &vh[0]);
                mma16816(O[2*jp+1], pl[kb], &vh[2]);
                mma16816(O[2*jp+1], ph[kb], &vl[2]);
                mma16816(O[2*jp+1], ph[kb], &vh[2]);
            }
        }
        __syncthreads();
        if (t + 2 < nk) FPF(t + 2, t & 1);
    }
    #undef FPF

    // ---- normalize + write z planes ----
    float inv0 = 1.f / ll0, inv1 = 1.f / ll1;
    int row0 = q0 + w*16 + g, row1 = row0 + 8;
    #pragma unroll
    for (int jd = 0; jd < 8; jd++) {
        int col = hh*DHEAD + jd*8 + 2*tg;
        float o0 = O[jd][0]*inv0, o1 = O[jd][1]*inv0;
        float o2 = O[jd][2]*inv1, o3 = O[jd][3]*inv1;
        *(uint32_t*)&g_zh[(size_t)row0*DMODEL + col] = pkh(o0, o1);
        *(uint32_t*)&g_zh[(size_t)row1*DMODEL + col] = pkh(o2, o3);
        *(uint32_t*)&g_zl[(size_t)row0*DMODEL + col] = pkl(o0, o1);
        *(uint32_t*)&g_zl[(size_t)row1*DMODEL + col] = pkl(o2, o3);
    }
}

// ---------------- output projection + unpatchify ----------------
__global__ void outproj_kernel(const float* __restrict__ Wout, const float* __restrict__ bout,
                               float* __restrict__ out) {
    __shared__ float row[DMODEL];
    int s = blockIdx.x, tid = threadIdx.x;
    for (int i = tid; i < DMODEL; i += 64) row[i] = g_h[(size_t)s * DMODEL + i];
    __syncthreads();
    if (tid < 48) {
        float acc = bout[tid];
        for (int k = 0; k < DMODEL; k++) acc += row[k] * Wout[k*48 + tid];
        int t = s >> 8, p = s & 255, oy = p >> 4, ox = p & 15;
        int c = tid >> 4, pi = (tid >> 2) & 3, pj = tid & 3;
        out[((t*3 + c)*64 + oy*4 + pi)*64 + ox*4 + pj] = acc;
    }
}

// ---------------- host ----------------
#define GEMM_SMEM (3*ST_B)
#define FLASH_SMEM (2*FSTG)

extern "C" void kernel_launch(void* const* d_in, const int* in_sizes, int n_in,
                              void* d_out, int out_size) {
    const float* x      = (const float*)d_in[0];
    const int*   actions= (const int*)  d_in[1];
    const float* ts     = (const float*)d_in[2];
    const float* conv_w = (const float*)d_in[3];
    const float* conv_b = (const float*)d_in[4];
    const float* pe     = (const float*)d_in[5];
    const float* ae     = (const float*)d_in[6];
    const float* Wmod   = (const float*)d_in[7];
    const float* bmod   = (const float*)d_in[8];
    const float* s1     = (const float*)d_in[9];
    const float* Wqkv   = (const float*)d_in[10];
    const float* Wo     = (const float*)d_in[11];
    const float* sq     = (const float*)d_in[12];
    const float* sk     = (const float*)d_in[13];
    const float* s2     = (const float*)d_in[14];
    const float* Wup    = (const float*)d_in[15];
    const float* Wgate  = (const float*)d_in[16];
    const float* Wdown  = (const float*)d_in[17];
    const float* s_final= (const float*)d_in[18];
    const float* Wmf    = (const float*)d_in[19];
    const float* bmf    = (const float*)d_in[20];
    const float* Wout   = (const float*)d_in[21];
    const float* bout   = (const float*)d_in[22];
    float* out = (float*)d_out;

    float *p_tokens, *p_cond, *p_mod, *p_h, *p_qkv, *p_u, *p_mf;
    __nv_bfloat16 *p_whi, *p_wlo, *p_hh, *p_hl, *p_zh, *p_zl, *p_acth, *p_actl;
    cudaGetSymbolAddress((void**)&p_tokens, g_tokens);
    cudaGetSymbolAddress((void**)&p_cond,   g_cond);
    cudaGetSymbolAddress((void**)&p_mod,    g_mod);
    cudaGetSymbolAddress((void**)&p_h,      g_h);
    cudaGetSymbolAddress((void**)&p_qkv,    g_qkv);
    cudaGetSymbolAddress((void**)&p_u,      g_u);
    cudaGetSymbolAddress((void**)&p_mf,     g_mf);
    cudaGetSymbolAddress((void**)&p_whi,    g_whi);
    cudaGetSymbolAddress((void**)&p_wlo,    g_wlo);
    cudaGetSymbolAddress((void**)&p_hh,     g_hh);
    cudaGetSymbolAddress((void**)&p_hl,     g_hl);
    cudaGetSymbolAddress((void**)&p_zh,     g_zh);
    cudaGetSymbolAddress((void**)&p_zl,     g_zl);
    cudaGetSymbolAddress((void**)&p_acth,   g_acth);
    cudaGetSymbolAddress((void**)&p_actl,   g_actl);

    cudaFuncSetAttribute(flash_tc, cudaFuncAttributeMaxDynamicSharedMemorySize, FLASH_SMEM);
    cudaFuncSetAttribute(gemm_bf16<0>, cudaFuncAttributeMaxDynamicSharedMemorySize, GEMM_SMEM);
    cudaFuncSetAttribute(gemm_bf16<1>, cudaFuncAttributeMaxDynamicSharedMemorySize, GEMM_SMEM);
    cudaFuncSetAttribute(gemm_bf16<2>, cudaFuncAttributeMaxDynamicSharedMemorySize, GEMM_SMEM);

    // ---- weight transpose + split: one launch per weight type, z = layer ----
    dim3 tb(32, 8);
    wsplit_kernel<<<dim3(2304/32, 768/32, NLAYER), tb>>>(Wqkv,  p_whi + OFF_QKV,  p_wlo + OFF_QKV,  768, 2304);
    wsplit_kernel<<<dim3( 768/32, 768/32, NLAYER), tb>>>(Wo,    p_whi + OFF_WO,   p_wlo + OFF_WO,   768,  768);
    wsplit_kernel<<<dim3(3072/32, 768/32, NLAYER), tb>>>(Wup,   p_whi + OFF_UP,   p_wlo + OFF_UP,   768, 3072);
    wsplit_kernel<<<dim3(3072/32, 768/32, NLAYER), tb>>>(Wgate, p_whi + OFF_GATE, p_wlo + OFF_GATE, 768, 3072);
    wsplit_kernel<<<dim3( 768/32, 3072/32, NLAYER), tb>>>(Wdown, p_whi + OFF_DOWN, p_wlo + OFF_DOWN, 3072, 768);

    patchify_kernel<<<SDIM, 256>>>(x, conv_w, conv_b, pe);
    cond_kernel<<<TFRM, 256>>>(actions, ts, ae);

    for (int l = 0; l < NLAYER; l++) {
        size_t lb = (size_t)l * LWSTRIDE;
        const float* bm  = bmod  + (size_t)l * MODW;
        const float* s1l = s1    + (size_t)l * DMODEL;
        const float* sql = sq    + (size_t)l * DHEAD;
        const float* skl = sk    + (size_t)l * DHEAD;
        const float* s2l = s2    + (size_t)l * DMODEL;

        smallm_gemm<<<MODW/128, 256>>>(p_cond, Wmod + (size_t)l*DMODEL*MODW, bm, p_mod, MODW);
        modulate_kernel<<<SDIM, 256>>>(p_tokens, p_h, s1l, p_mod, MODW, 0, 768);
        gemm_bf16<0><<<dim3(2304/128, SDIM/128, 1), 256, GEMM_SMEM>>>(
            p_hh, p_hl, p_whi + lb + OFF_QKV, p_wlo + lb + OFF_QKV,
            p_qkv, SDIM, 2304, 768, 768, nullptr, nullptr, nullptr);
        splitnorm_kernel<<<dim3(SDIM, NHEAD), 64>>>(sql, skl);
        flash_tc<<<dim3(SDIM/64, NHEAD), 128, FLASH_SMEM>>>();
        // Wo: split-K x2 into g_u partials, then combine into tokens
        gemm_bf16<0><<<dim3(768/128, SDIM/128, 2), 256, GEMM_SMEM>>>(
            p_zh, p_zl, p_whi + lb + OFF_WO, p_wlo + lb + OFF_WO,
            p_u, SDIM, 768, 384, 768, nullptr, nullptr, nullptr);
        combineK<<<SDIM*DMODEL/1024, 256>>>(p_u, p_tokens, p_mod, 1536);
        modulate_kernel<<<SDIM, 256>>>(p_tokens, p_h, s2l, p_mod, MODW, 2304, 3072);
        gemm_bf16<0><<<dim3(3072/128, SDIM/128, 1), 256, GEMM_SMEM>>>(
            p_hh, p_hl, p_whi + lb + OFF_UP, p_wlo + lb + OFF_UP,
            p_u, SDIM, 3072, 768, 768, nullptr, nullptr, nullptr);
        gemm_bf16<2><<<dim3(3072/128, SDIM/128, 1), 256, GEMM_SMEM>>>(
            p_hh, p_hl, p_whi + lb + OFF_GATE, p_wlo + lb + OFF_GATE,
            nullptr, SDIM, 3072, 768, 768, p_u, p_acth, p_actl);
        // down: split-K x2 into g_u partials (u already consumed by gate epilogue), then combine
        gemm_bf16<0><<<dim3(768/128, SDIM/128, 2), 256, GEMM_SMEM>>>(
            p_acth, p_actl, p_whi + lb + OFF_DOWN, p_wlo + lb + OFF_DOWN,
            p_u, SDIM, 768, 1536, 3072, nullptr, nullptr, nullptr);
        combineK<<<SDIM*DMODEL/1024, 256>>>(p_u, p_tokens, p_mod, 3840);
    }

    smallm_gemm<<<2*DMODEL/128, 256>>>(p_cond, Wmf, bmf, p_mf, 2*DMODEL);
    modulate_kernel<<<SDIM, 256>>>(p_tokens, p_h, s_final, p_mf, 2*DMODEL, 0, 768);
    outproj_kernel<<<SDIM, 64>>>(Wout, bout, out);
}

// round 13
// speedup vs baseline: 2.6688x; 1.0077x over previous
#include <cuda_runtime.h>
#include <cuda_bf16.h>
#include <math.h>
#include <stdint.h>

// ---------------- constants ----------------
#define DMODEL 768
#define NHEAD  12
#define DHEAD  64
#define NLAYER 4
#define PPF    256
#define SDIM   2048
#define TFRM   8
#define EXPD   3072
#define MODW   4608
#define EPSV   1e-6f

#define LWSTRIDE 9437184
#define OFF_QKV  0
#define OFF_WO   1769472
#define OFF_UP   2359296
#define OFF_GATE 4718592
#define OFF_DOWN 7077888

// ---------------- scratch ----------------
__device__ float g_tokens[SDIM*DMODEL];
__device__ float g_cond[TFRM*DMODEL];
__device__ float g_mod[NLAYER*TFRM*MODW];
__device__ float g_h[SDIM*DMODEL];
__device__ float g_qkv[SDIM*3*DMODEL];
__device__ float g_u[SDIM*EXPD];        // up output; reused as 3-slice split-K partial buffer
__device__ float g_mf[TFRM*2*DMODEL];

__device__ __nv_bfloat16 g_whi[4*LWSTRIDE];
__device__ __nv_bfloat16 g_wlo[4*LWSTRIDE];
__device__ __nv_bfloat16 g_hh[SDIM*DMODEL],  g_hl[SDIM*DMODEL];
__device__ __nv_bfloat16 g_zh[SDIM*DMODEL],  g_zl[SDIM*DMODEL];
__device__ __nv_bfloat16 g_acth[SDIM*EXPD],  g_actl[SDIM*EXPD];
__device__ __nv_bfloat16 g_qph[NHEAD*SDIM*DHEAD], g_qpl[NHEAD*SDIM*DHEAD];
__device__ __nv_bfloat16 g_kph[NHEAD*SDIM*DHEAD], g_kpl[NHEAD*SDIM*DHEAD];
__device__ __nv_bfloat16 g_vph[NHEAD*SDIM*DHEAD], g_vpl[NHEAD*SDIM*DHEAD];

// ---------------- helpers ----------------
__device__ __forceinline__ void cp16(uint32_t d, const void* s) {
    asm volatile("cp.async.cg.shared.global [%0], [%1], 16;" :: "r"(d), "l"(s));
}
__device__ __forceinline__ void ldsm4(uint32_t* r, uint32_t a) {
    asm volatile("ldmatrix.sync.aligned.m8n8.x4.shared.b16 {%0,%1,%2,%3}, [%4];"
                 : "=r"(r[0]), "=r"(r[1]), "=r"(r[2]), "=r"(r[3]) : "r"(a));
}
__device__ __forceinline__ void ldsm4t(uint32_t* r, uint32_t a) {
    asm volatile("ldmatrix.sync.aligned.m8n8.x4.trans.shared.b16 {%0,%1,%2,%3}, [%4];"
                 : "=r"(r[0]), "=r"(r[1]), "=r"(r[2]), "=r"(r[3]) : "r"(a));
}
__device__ __forceinline__ void mma16816(float* d, const uint32_t* a, const uint32_t* b) {
    asm volatile("mma.sync.aligned.m16n8k16.row.col.f32.bf16.bf16.f32 "
        "{%0,%1,%2,%3}, {%4,%5,%6,%7}, {%8,%9}, {%0,%1,%2,%3};"
        : "+f"(d[0]), "+f"(d[1]), "+f"(d[2]), "+f"(d[3])
        : "r"(a[0]), "r"(a[1]), "r"(a[2]), "r"(a[3]), "r"(b[0]), "r"(b[1]));
}
__device__ __forceinline__ uint32_t pkh(float a, float b) {
    __nv_bfloat162 t; t.x = __float2bfloat16(a); t.y = __float2bfloat16(b);
    return *(uint32_t*)&t;
}
__device__ __forceinline__ uint32_t pkl(float a, float b) {
    float ra = a - __bfloat162float(__float2bfloat16(a));
    float rb = b - __bfloat162float(__float2bfloat16(b));
    return pkh(ra, rb);
}

// ---------------- weight transpose + bf16 hi/lo split (z = layer) ----------------
__global__ void wsplit_kernel(const float* __restrict__ W, __nv_bfloat16* __restrict__ oh,
                              __nv_bfloat16* __restrict__ ol, int K, int N) {
    int l = blockIdx.z;
    W  += (size_t)l * K * N;
    oh += (size_t)l * LWSTRIDE;
    ol += (size_t)l * LWSTRIDE;
    __shared__ float t[32][33];
    int n0 = blockIdx.x*32, k0 = blockIdx.y*32;
    int tx = threadIdx.x, ty = threadIdx.y;
    #pragma unroll
    for (int r = ty; r < 32; r += 8) t[r][tx] = W[(size_t)(k0+r)*N + n0+tx];
    __syncthreads();
    #pragma unroll
    for (int r = ty; r < 32; r += 8) {
        float v = t[tx][r];
        __nv_bfloat16 h = __float2bfloat16(v);
        size_t o = (size_t)(n0+r)*K + k0+tx;
        oh[o] = h; ol[o] = __float2bfloat16(v - __bfloat162float(h));
    }
}

// ---------------- patchify ----------------
__global__ void patchify_kernel(const float* __restrict__ x, const float* __restrict__ cw,
                                const float* __restrict__ cb, const float* __restrict__ pe) {
    int s = blockIdx.x;
    int t = s >> 8, p = s & 255, oy = p >> 4, ox = p & 15;
    __shared__ float patch[75];
    int tid = threadIdx.x;
    if (tid < 75) {
        int c = tid / 25, rem = tid % 25, r = rem / 5, w = rem % 5;
        int iy = oy*4 - 2 + r, ix = ox*4 - 2 + w;
        float v = 0.f;
        if (iy >= 0 && iy < 64 && ix >= 0 && ix < 64)
            v = x[((t*3 + c)*64 + iy)*64 + ix];
        patch[tid] = v;
    }
    __syncthreads();
    for (int d = tid; d < DMODEL; d += 256) {
        float acc = cb[d];
        const float* w = cw + d*75;
        #pragma unroll
        for (int i = 0; i < 75; i++) acc += patch[i] * w[i];
        g_tokens[s*DMODEL + d] = acc + pe[p*DMODEL + d];
    }
}

// ---------------- conditioning ----------------
__global__ void cond_kernel(const int* __restrict__ actions, const float* __restrict__ ts,
                            const float* __restrict__ ae) {
    int f = blockIdx.x;
    int a = actions[f];
    float tsv = ts[f];
    int ti = (int)(tsv * 1000.0f);
    if (ti > 999) ti = 999;
    float tif = (float)ti;
    for (int d = threadIdx.x; d < DMODEL; d += blockDim.x) {
        int j = (d < 384) ? d : d - 384;
        float th = powf(500.0f, -((float)j) / 384.0f);
        float ang = tif * th;
        float te = (d < 384) ? sinf(ang) : cosf(ang);
        float c = te + ae[a*DMODEL + d];
        g_cond[f*DMODEL + d] = c / (1.f + expf(-c));
    }
}

// ---------------- small-M GEMM: C[8,N] = cond @ B + bias ----------------
__global__ void smallm_gemm(const float* __restrict__ A, const float* __restrict__ B,
                            const float* __restrict__ bias, float* __restrict__ C, int N) {
    __shared__ float As[8*DMODEL];
    int tid = threadIdx.x;
    for (int i = tid; i < 8*DMODEL; i += 256) As[i] = A[i];
    __syncthreads();
    int col = tid & 127, rg = tid >> 7;
    int n = blockIdx.x * 128 + col;
    float acc0 = 0, acc1 = 0, acc2 = 0, acc3 = 0;
    int rb = rg * 4;
    for (int k = 0; k < DMODEL; k++) {
        float bv = B[(size_t)k * N + n];
        acc0 += As[(rb+0)*DMODEL + k] * bv;
        acc1 += As[(rb+1)*DMODEL + k] * bv;
        acc2 += As[(rb+2)*DMODEL + k] * bv;
        acc3 += As[(rb+3)*DMODEL + k] * bv;
    }
    float bs = bias[n];
    C[(rb+0)*N + n] = acc0 + bs;
    C[(rb+1)*N + n] = acc1 + bs;
    C[(rb+2)*N + n] = acc2 + bs;
    C[(rb+3)*N + n] = acc3 + bs;
}

// ---------------- RMSNorm + AdaLN modulate (layer0 entry; writes fp32 + planes) ----------------
__global__ void modulate_kernel(const float* __restrict__ in, float* __restrict__ out,
                                const float* __restrict__ sa, const float* __restrict__ mod,
                                int mstride, int off_sc, int off_b) {
    int s = blockIdx.x, tid = threadIdx.x, f = s >> 8;
    const float* row = in + (size_t)s * DMODEL;
    float v0 = row[tid], v1 = row[tid+256], v2 = row[tid+512];
    float ss = v0*v0 + v1*v1 + v2*v2;
    __shared__ float red[8];
    #pragma unroll
    for (int o = 16; o > 0; o >>= 1) ss += __shfl_xor_sync(0xffffffffu, ss, o);
    if ((tid & 31) == 0) red[tid >> 5] = ss;
    __syncthreads();
    float tot = 0.f;
    #pragma unroll
    for (int w = 0; w < 8; w++) tot += red[w];
    float rinv = 1.f / (sqrtf(tot * (1.f/768.f)) + EPSV);
    const float* mrow = mod + f * mstride;
    float* orow = out + (size_t)s * DMODEL;
    size_t base = (size_t)s * DMODEL;
    #pragma unroll
    for (int c = 0; c < 3; c++) {
        int d = tid + c*256;
        float v = (c == 0) ? v0 : (c == 1 ? v1 : v2);
        float o = v * rinv * sa[d] * (1.f + mrow[off_sc + d]) + mrow[off_b + d];
        orow[d] = o;
        __nv_bfloat16 h = __float2bfloat16(o);
        g_hh[base + d] = h;
        g_hl[base + d] = __float2bfloat16(o - __bfloat162float(h));
    }
}

// ---------------- fused split-K combine + residual gate + RMSNorm-modulate ----------------
__global__ void fusedCM(const float* __restrict__ P,
                        const float* __restrict__ gate, int gstride,
                        const float* __restrict__ sa,
                        const float* __restrict__ msb, int mstride, int off_sc, int off_b,
                        float* __restrict__ hout) {
    int s = blockIdx.x, tid = threadIdx.x, f = s >> 8;
    size_t base = (size_t)s * DMODEL;
    const float* grow = gate + f * gstride;
    float v[3]; float ss = 0.f;
    #pragma unroll
    for (int c = 0; c < 3; c++) {
        int d = tid + c*256;
        float p = P[base + d] + P[(size_t)SDIM*DMODEL + base + d] + P[2*(size_t)SDIM*DMODEL + base + d];
        float t = g_tokens[base + d] + p * grow[d];
        g_tokens[base + d] = t;
        v[c] = t; ss += t*t;
    }
    __shared__ float red[8];
    #pragma unroll
    for (int o = 16; o > 0; o >>= 1) ss += __shfl_xor_sync(0xffffffffu, ss, o);
    if ((tid & 31) == 0) red[tid >> 5] = ss;
    __syncthreads();
    float tot = 0.f;
    #pragma unroll
    for (int w = 0; w < 8; w++) tot += red[w];
    float rinv = 1.f / (sqrtf(tot * (1.f/768.f)) + EPSV);
    const float* mrow = msb + f * mstride;
    #pragma unroll
    for (int c = 0; c < 3; c++) {
        int d = tid + c*256;
        float o = v[c] * rinv * sa[d] * (1.f + mrow[off_sc + d]) + mrow[off_b + d];
        if (hout) hout[base + d] = o;
        __nv_bfloat16 h = __float2bfloat16(o);
        g_hh[base + d] = h;
        g_hl[base + d] = __float2bfloat16(o - __bfloat162float(h));
    }
}

// ---------------- bf16 3-term split tensor-core GEMM: k32 stages, 2-deep, 1 sync/32K ----------------
#define PL_B  10240   // plane bytes: 128 rows x 80B (64B data + 16B pad, odd 16B stride)
#define ST_B  40960   // stage = 4 planes

template<int EPI>
__global__ void __launch_bounds__(256) gemm_bf16(
    const __nv_bfloat16* __restrict__ Agh, const __nv_bfloat16* __restrict__ Agl,
    const __nv_bfloat16* __restrict__ Bgh, const __nv_bfloat16* __restrict__ Bgl,
    float* __restrict__ C, int M, int N, int K, int ld,
    const float* __restrict__ aux,
    __nv_bfloat16* __restrict__ Oh, __nv_bfloat16* __restrict__ Ol)
{
    extern __shared__ __align__(16) __nv_bfloat16 smem[];
    int tid = threadIdx.x, lane = tid & 31, wid = tid >> 5;
    int m0 = blockIdx.y * 128, n0 = blockIdx.x * 128;
    int kz = blockIdx.z;
    int wm = wid >> 2, wn = wid & 3, g = lane >> 2, tg = lane & 3;

    float acc[4][4][4];
    #pragma unroll
    for (int i = 0; i < 4; i++)
        #pragma unroll
        for (int j = 0; j < 4; j++)
            #pragma unroll
            for (int c = 0; c < 4; c++) acc[i][j][c] = 0.f;

    int c0 = tid*2, c1 = tid*2 + 1;
    int r0_ = c0 >> 2, q0_ = c0 & 3, r1_ = c1 >> 2, q1_ = c1 & 3;
    uint32_t d0 = (uint32_t)r0_*80 + q0_*16, d1 = (uint32_t)r1_*80 + q1_*16;
    size_t kb0 = (size_t)kz * K;
    size_t gA0 = (size_t)(m0 + r0_) * ld + kb0 + q0_*8;
    size_t gA1 = (size_t)(m0 + r1_) * ld + kb0 + q1_*8;
    size_t gB0 = (size_t)(n0 + r0_) * ld + kb0 + q0_*8;
    size_t gB1 = (size_t)(n0 + r1_) * ld + kb0 + q1_*8;
    uint32_t sbase = (uint32_t)__cvta_generic_to_shared(smem);

    int NK = K >> 5;

    #define PF(st, kc) { \
        uint32_t b_ = sbase + (st)*ST_B; \
        cp16(b_ + d0,          Agh + gA0 + (kc)); \
        cp16(b_ + d1,          Agh + gA1 + (kc)); \
        cp16(b_ + PL_B + d0,   Agl + gA0 + (kc)); \
        cp16(b_ + PL_B + d1,   Agl + gA1 + (kc)); \
        cp16(b_ + 2*PL_B + d0, Bgh + gB0 + (kc)); \
        cp16(b_ + 2*PL_B + d1, Bgh + gB1 + (kc)); \
        cp16(b_ + 3*PL_B + d0, Bgl + gB0 + (kc)); \
        cp16(b_ + 3*PL_B + d1, Bgl + gB1 + (kc)); \
        asm volatile("cp.async.commit_group;"); }

    PF(0, 0);

    int a_row = (lane & 7) + ((lane >> 3) & 1) * 8;
    int a_kb  = ((lane >> 4) & 1) * 16;
    int b_row = (lane & 7) + ((lane >> 4) & 1) * 8;
    int b_kb  = ((lane >> 3) & 1) * 16;
    uint32_t aoffA = (uint32_t)(wm*64 + a_row) * 80 + a_kb;
    uint32_t aoffB = (uint32_t)(wn*32 + b_row) * 80 + b_kb;

    int st = 0;
    for (int ks = 0; ks < NK; ks++) {
        asm volatile("cp.async.wait_group 0;");
        __syncthreads();
        if (ks + 1 < NK) PF(st ^ 1, (ks+1)*32);
        uint32_t base = sbase + st*ST_B;
        #pragma unroll
        for (int h = 0; h < 2; h++) {
            uint32_t hb = h*32;
            uint32_t bh[4][2], bl[4][2];
            #pragma unroll
            for (int jp = 0; jp < 2; jp++) {
                uint32_t ad = base + 2*PL_B + aoffB + jp*1280 + hb;
                uint32_t t0[4], t1[4];
                ldsm4(t0, ad);
                ldsm4(t1, ad + PL_B);
                bh[2*jp][0]=t0[0]; bh[2*jp][1]=t0[1]; bh[2*jp+1][0]=t0[2]; bh[2*jp+1][1]=t0[3];
                bl[2*jp][0]=t1[0]; bl[2*jp][1]=t1[1]; bl[2*jp+1][0]=t1[2]; bl[2*jp+1][1]=t1[3];
            }
            #pragma unroll
            for (int i = 0; i < 4; i++) {
                uint32_t ah[4], al[4];
                uint32_t ad = base + aoffA + i*1280 + hb;
                ldsm4(ah, ad);
                ldsm4(al, ad + PL_B);
                #pragma unroll
                for (int j = 0; j < 4; j++) {
                    mma16816(acc[i][j], al, bh[j]);
                    mma16816(acc[i][j], ah, bl[j]);
                    mma16816(acc[i][j], ah, bh[j]);
                }
            }
        }
        st ^= 1;
    }
    #undef PF

    C += (size_t)kz * M * N;
    #pragma unroll
    for (int i = 0; i < 4; i++) {
        int r0 = m0 + wm*64 + i*16 + g;
        int r1 = r0 + 8;
        #pragma unroll
        for (int j = 0; j < 4; j++) {
            int col = n0 + wn*32 + j*8 + 2*tg;
            if (EPI == 0) {
                *(float2*)&C[(size_t)r0*N + col] = make_float2(acc[i][j][0], acc[i][j][1]);
                *(float2*)&C[(size_t)r1*N + col] = make_float2(acc[i][j][2], acc[i][j][3]);
            } else {
                const float* u0 = aux + (size_t)r0*N + col;
                const float* u1 = aux + (size_t)r1*N + col;
                float v, o0, o1, o2, o3;
                v = acc[i][j][0]; o0 = u0[0] * (v / (1.f + __expf(-v)));
                v = acc[i][j][1]; o1 = u0[1] * (v / (1.f + __expf(-v)));
                v = acc[i][j][2]; o2 = u1[0] * (v / (1.f + __expf(-v)));
                v = acc[i][j][3]; o3 = u1[1] * (v / (1.f + __expf(-v)));
                *(uint32_t*)&Oh[(size_t)r0*N + col] = pkh(o0, o1);
                *(uint32_t*)&Oh[(size_t)r1*N + col] = pkh(o2, o3);
                *(uint32_t*)&Ol[(size_t)r0*N + col] = pkl(o0, o1);
                *(uint32_t*)&Ol[(size_t)r1*N + col] = pkl(o2, o3);
            }
        }
    }
}

// ---------------- qkv split + per-head RMSNorm -> bf16 hi/lo planes [h][s][64] ----------------
__global__ void splitnorm_kernel(const float* __restrict__ sq, const float* __restrict__ sk) {
    int s = blockIdx.x, hh = blockIdx.y, d = threadIdx.x;
    const float* base = g_qkv + (size_t)s * (3*DMODEL) + hh * DHEAD;
    float qv = base[d], kv = base[DMODEL + d], vv = base[2*DMODEL + d];
    __shared__ float red[4];
    float qs = qv * qv, ks = kv * kv;
    #pragma unroll
    for (int o = 16; o > 0; o >>= 1) {
        qs += __shfl_xor_sync(0xffffffffu, qs, o);
        ks += __shfl_xor_sync(0xffffffffu, ks, o);
    }
    if ((d & 31) == 0) { red[d >> 5] = qs; red[2 + (d >> 5)] = ks; }
    __syncthreads();
    float qr = 1.f / (sqrtf((red[0]+red[1]) * (1.f/64.f)) + EPSV);
    float kr = 1.f / (sqrtf((red[2]+red[3]) * (1.f/64.f)) + EPSV);
    float qo = qv * qr * sq[d];
    float ko = kv * kr * sk[d];
    size_t o = ((size_t)hh * SDIM + s) * DHEAD + d;
    __nv_bfloat16 h;
    h = __float2bfloat16(qo); g_qph[o] = h; g_qpl[o] = __float2bfloat16(qo - __bfloat162float(h));
    h = __float2bfloat16(ko); g_kph[o] = h; g_kpl[o] = __float2bfloat16(ko - __bfloat162float(h));
    h = __float2bfloat16(vv); g_vph[o] = h; g_vpl[o] = __float2bfloat16(vv - __bfloat162float(h));
}

// ---------------- tensor-core flash attention (block-causal, unscaled) ----------------
#define FROW 144
#define FPL  9216
#define FSTG 36864

__global__ void __launch_bounds__(128) flash_tc() {
    extern __shared__ __align__(16) char fsm[];
    int tid = threadIdx.x, lane = tid & 31, w = tid >> 5;
    int qb = blockIdx.x, hh = blockIdx.y;
    int q0 = qb * 64;
    int nk = ((qb >> 2) + 1) * 4;
    int g = lane >> 2, tg = lane & 3;
    uint32_t sb = (uint32_t)__cvta_generic_to_shared(fsm);
    size_t hbase = (size_t)hh * SDIM;

    #pragma unroll
    for (int i = 0; i < 4; i++) {
        int ch = i*128 + tid, r = ch >> 3, hf = ch & 7;
        cp16(sb + r*FROW + hf*16,       g_qph + (hbase + q0 + r)*DHEAD + hf*8);
        cp16(sb + FPL + r*FROW + hf*16, g_qpl + (hbase + q0 + r)*DHEAD + hf*8);
    }
    asm volatile("cp.async.commit_group;");
    asm volatile("cp.async.wait_group 0;");
    __syncthreads();

    int a_row = (lane & 7) + ((lane >> 3) & 1) * 8;
    int a_kb  = ((lane >> 4) & 1) * 16;
    uint32_t qh[4][4], ql[4][4];
    {
        uint32_t qoff = sb + (uint32_t)(w*16 + a_row)*FROW + a_kb;
        #pragma unroll
        for (int kb = 0; kb < 4; kb++) {
            ldsm4(qh[kb], qoff + kb*32);
            ldsm4(ql[kb], qoff + FPL + kb*32);
        }
    }
    __syncthreads();

    #define FPF(t, buf) { \
        uint32_t bb = sb + (buf)*FSTG; \
        size_t gsrc = (hbase + (t)*64) * DHEAD; \
        _Pragma("unroll") \
        for (int i = 0; i < 4; i++) { \
            int ch = i*128 + tid, r = ch >> 3, hf = ch & 7; \
            uint32_t so = r*FROW + hf*16; size_t go = gsrc + r*DHEAD + hf*8; \
            cp16(bb + so,         g_kph + go); \
            cp16(bb + FPL + so,   g_kpl + go); \
            cp16(bb + 2*FPL + so, g_vph + go); \
            cp16(bb + 3*FPL + so, g_vpl + go); \
        } \
        asm volatile("cp.async.commit_group;"); }

    FPF(0, 0); FPF(1, 1);

    int b_row = (lane & 7) + ((lane >> 4) & 1) * 8;
    int b_kb  = ((lane >> 3) & 1) * 16;
    int v_srow = (lane & 7) + ((lane >> 3) & 1) * 8;
    int v_dcol = ((lane >> 4) & 1) * 8;

    float O[8][4];
    #pragma unroll
    for (int j = 0; j < 8; j++)
        #pragma unroll
        for (int c = 0; c < 4; c++) O[j][c] = 0.f;
    float mm0 = -1e30f, mm1 = -1e30f, ll0 = 0.f, ll1 = 0.f;

    for (int t = 0; t < nk; t++) {
        if (t + 1 < nk) asm volatile("cp.async.wait_group 1;");
        else            asm volatile("cp.async.wait_group 0;");
        __syncthreads();
        uint32_t bb = sb + (t & 1)*FSTG;

        float S[8][4];
        #pragma unroll
        for (int j = 0; j < 8; j++)
            #pragma unroll
            for (int c = 0; c < 4; c++) S[j][c] = 0.f;
        #pragma unroll
        for (int jp = 0; jp < 4; jp++) {
            #pragma unroll
            for (int kb = 0; kb < 4; kb++) {
                uint32_t kh[4], kl[4];
                uint32_t ad = bb + (uint32_t)(jp*16 + b_row)*FROW + b_kb + kb*32;
                ldsm4(kh, ad);
                ldsm4(kl, ad + FPL);
                mma16816(S[2*jp],   ql[kb], &kh[0]);
                mma16816(S[2*jp],   qh[kb], &kl[0]);
                mma16816(S[2*jp],   qh[kb], &kh[0]);
                mma16816(S[2*jp+1], ql[kb], &kh[2]);
                mma16816(S[2*jp+1], qh[kb], &kl[2]);
                mma16816(S[2*jp+1], qh[kb], &kh[2]);
            }
        }

        float mx0 = -1e30f, mx1 = -1e30f;
        #pragma unroll
        for (int j = 0; j < 8; j++) {
            mx0 = fmaxf(mx0, fmaxf(S[j][0], S[j][1]));
            mx1 = fmaxf(mx1, fmaxf(S[j][2], S[j][3]));
        }
        #pragma unroll
        for (int o = 1; o < 4; o <<= 1) {
            mx0 = fmaxf(mx0, __shfl_xor_sync(0xffffffffu, mx0, o));
            mx1 = fmaxf(mx1, __shfl_xor_sync(0xffffffffu, mx1, o));
        }
        float mn0 = fmaxf(mm0, mx0), mn1 = fmaxf(mm1, mx1);
        float sc0 = __expf(mm0 - mn0), sc1 = __expf(mm1 - mn1);
        mm0 = mn0; mm1 = mn1;
        float rs0 = 0.f, rs1 = 0.f;
        #pragma unroll
        for (int j = 0; j < 8; j++) {
            S[j][0] = __expf(S[j][0] - mn0); rs0 += S[j][0];
            S[j][1] = __expf(S[j][1] - mn0); rs0 += S[j][1];
            S[j][2] = __expf(S[j][2] - mn1); rs1 += S[j][2];
            S[j][3] = __expf(S[j][3] - mn1); rs1 += S[j][3];
        }
        #pragma unroll
        for (int o = 1; o < 4; o <<= 1) {
            rs0 += __shfl_xor_sync(0xffffffffu, rs0, o);
            rs1 += __shfl_xor_sync(0xffffffffu, rs1, o);
        }
        ll0 = ll0 * sc0 + rs0;
        ll1 = ll1 * sc1 + rs1;
        #pragma unroll
        for (int j = 0; j < 8; j++) {
            O[j][0] *= sc0; O[j][1] *= sc0;
            O[j][2] *= sc1; O[j][3] *= sc1;
        }

        uint32_t ph[4][4], pl[4][4];
        #pragma unroll
        for (int kb = 0; kb < 4; kb++) {
            ph[kb][0] = pkh(S[2*kb][0],   S[2*kb][1]);
            ph[kb][1] = pkh(S[2*kb][2],   S[2*kb][3]);
            ph[kb][2] = pkh(S[2*kb+1][0], S[2*kb+1][1]);
            ph[kb][3] = pkh(S[2*kb+1][2], S[2*kb+1][3]);
            pl[kb][0] = pkl(S[2*kb][0],   S[2*kb][1]);
            pl[kb][1] = pkl(S[2*kb][2],   S[2*kb][3]);
            pl[kb][2] = pkl(S[2*kb+1][0], S[2*kb+1][1]);
            pl[kb][3] = pkl(S[2*kb+1][2], S[2*kb+1][3]);
        }

        #pragma unroll
        for (int jp = 0; jp < 4; jp++) {
            #pragma unroll
            for (int kb = 0; kb < 4; kb++) {
                uint32_t vh[4], vl[4];
                uint32_t ad = bb + 2*FPL + (uint32_t)(kb*16 + v_srow)*FROW + (uint32_t)(jp*16 + v_dcol)*2;
                ldsm4t(vh, ad);
                ldsm4t(vl, ad + FPL);
                mma16816(O[2*jp],   pl[kb], &vh[0]);
                mma16816(O[2*jp],   ph[kb], &vl[0]);
                mma16816(O[2*jp],   ph[kb], &vh[0]);
                mma16816(O[2*jp+1], pl[kb], &vh[2]);
                mma16816(O[2*jp+1], ph[kb], &vl[2]);
                mma16816(O[2*jp+1], ph[kb], &vh[2]);
            }
        }
        __syncthreads();
        if (t + 2 < nk) FPF(t + 2, t & 1);
    }
    #undef FPF

    float inv0 = 1.f / ll0, inv1 = 1.f / ll1;
    int row0 = q0 + w*16 + g, row1 = row0 + 8;
    #pragma unroll
    for (int jd = 0; jd < 8; jd++) {
        int col = hh*DHEAD + jd*8 + 2*tg;
        float o0 = O[jd][0]*inv0, o1 = O[jd][1]*inv0;
        float o2 = O[jd][2]*inv1, o3 = O[jd][3]*inv1;
        *(uint32_t*)&g_zh[(size_t)row0*DMODEL + col] = pkh(o0, o1);
        *(uint32_t*)&g_zh[(size_t)row1*DMODEL + col] = pkh(o2, o3);
        *(uint32_t*)&g_zl[(size_t)row0*DMODEL + col] = pkl(o0, o1);
        *(uint32_t*)&g_zl[(size_t)row1*DMODEL + col] = pkl(o2, o3);
    }
}

// ---------------- output projection + unpatchify ----------------
__global__ void outproj_kernel(const float* __restrict__ Wout, const float* __restrict__ bout,
                               float* __restrict__ out) {
    __shared__ float row[DMODEL];
    int s = blockIdx.x, tid = threadIdx.x;
    for (int i = tid; i < DMODEL; i += 64) row[i] = g_h[(size_t)s * DMODEL + i];
    __syncthreads();
    if (tid < 48) {
        float acc = bout[tid];
        for (int k = 0; k < DMODEL; k++) acc += row[k] * Wout[k*48 + tid];
        int t = s >> 8, p = s & 255, oy = p >> 4, ox = p & 15;
        int c = tid >> 4, pi = (tid >> 2) & 3, pj = tid & 3;
        out[((t*3 + c)*64 + oy*4 + pi)*64 + ox*4 + pj] = acc;
    }
}

// ---------------- host ----------------
#define GEMM_SMEM (2*ST_B)
#define FLASH_SMEM (2*FSTG)

extern "C" void kernel_launch(void* const* d_in, const int* in_sizes, int n_in,
                              void* d_out, int out_size) {
    const float* x      = (const float*)d_in[0];
    const int*   actions= (const int*)  d_in[1];
    const float* ts     = (const float*)d_in[2];
    const float* conv_w = (const float*)d_in[3];
    const float* conv_b = (const float*)d_in[4];
    const float* pe     = (const float*)d_in[5];
    const float* ae     = (const float*)d_in[6];
    const float* Wmod   = (const float*)d_in[7];
    const float* bmod   = (const float*)d_in[8];
    const float* s1     = (const float*)d_in[9];
    const float* Wqkv   = (const float*)d_in[10];
    const float* Wo     = (const float*)d_in[11];
    const float* sq     = (const float*)d_in[12];
    const float* sk     = (const float*)d_in[13];
    const float* s2     = (const float*)d_in[14];
    const float* Wup    = (const float*)d_in[15];
    const float* Wgate  = (const float*)d_in[16];
    const float* Wdown  = (const float*)d_in[17];
    const float* s_final= (const float*)d_in[18];
    const float* Wmf    = (const float*)d_in[19];
    const float* bmf    = (const float*)d_in[20];
    const float* Wout   = (const float*)d_in[21];
    const float* bout   = (const float*)d_in[22];
    float* out = (float*)d_out;

    float *p_tokens, *p_cond, *p_mod, *p_h, *p_qkv, *p_u, *p_mf;
    __nv_bfloat16 *p_whi, *p_wlo, *p_hh, *p_hl, *p_zh, *p_zl, *p_acth, *p_actl;
    cudaGetSymbolAddress((void**)&p_tokens, g_tokens);
    cudaGetSymbolAddress((void**)&p_cond,   g_cond);
    cudaGetSymbolAddress((void**)&p_mod,    g_mod);
    cudaGetSymbolAddress((void**)&p_h,      g_h);
    cudaGetSymbolAddress((void**)&p_qkv,    g_qkv);
    cudaGetSymbolAddress((void**)&p_u,      g_u);
    cudaGetSymbolAddress((void**)&p_mf,     g_mf);
    cudaGetSymbolAddress((void**)&p_whi,    g_whi);
    cudaGetSymbolAddress((void**)&p_wlo,    g_wlo);
    cudaGetSymbolAddress((void**)&p_hh,     g_hh);
    cudaGetSymbolAddress((void**)&p_hl,     g_hl);
    cudaGetSymbolAddress((void**)&p_zh,     g_zh);
    cudaGetSymbolAddress((void**)&p_zl,     g_zl);
    cudaGetSymbolAddress((void**)&p_acth,   g_acth);
    cudaGetSymbolAddress((void**)&p_actl,   g_actl);

    cudaFuncSetAttribute(flash_tc, cudaFuncAttributeMaxDynamicSharedMemorySize, FLASH_SMEM);
    cudaFuncSetAttribute(gemm_bf16<0>, cudaFuncAttributeMaxDynamicSharedMemorySize, GEMM_SMEM);
    cudaFuncSetAttribute(gemm_bf16<2>, cudaFuncAttributeMaxDynamicSharedMemorySize, GEMM_SMEM);

    dim3 tb(32, 8);
    wsplit_kernel<<<dim3(2304/32, 768/32, NLAYER), tb>>>(Wqkv,  p_whi + OFF_QKV,  p_wlo + OFF_QKV,  768, 2304);
    wsplit_kernel<<<dim3( 768/32, 768/32, NLAYER), tb>>>(Wo,    p_whi + OFF_WO,   p_wlo + OFF_WO,   768,  768);
    wsplit_kernel<<<dim3(3072/32, 768/32, NLAYER), tb>>>(Wup,   p_whi + OFF_UP,   p_wlo + OFF_UP,   768, 3072);
    wsplit_kernel<<<dim3(3072/32, 768/32, NLAYER), tb>>>(Wgate, p_whi + OFF_GATE, p_wlo + OFF_GATE, 768, 3072);
    wsplit_kernel<<<dim3( 768/32, 3072/32, NLAYER), tb>>>(Wdown, p_whi + OFF_DOWN, p_wlo + OFF_DOWN, 3072, 768);

    patchify_kernel<<<SDIM, 256>>>(x, conv_w, conv_b, pe);
    cond_kernel<<<TFRM, 256>>>(actions, ts, ae);

    for (int l = 0; l < NLAYER; l++)
        smallm_gemm<<<MODW/128, 256>>>(p_cond, Wmod + (size_t)l*DMODEL*MODW,
                                       bmod + (size_t)l*MODW, p_mod + (size_t)l*TFRM*MODW, MODW);
    smallm_gemm<<<2*DMODEL/128, 256>>>(p_cond, Wmf, bmf, p_mf, 2*DMODEL);

    for (int l = 0; l < NLAYER; l++) {
        size_t lb = (size_t)l * LWSTRIDE;
        float* modl = p_mod + (size_t)l * TFRM * MODW;
        const float* sql = sq + (size_t)l * DHEAD;
        const float* skl = sk + (size_t)l * DHEAD;
        const float* s2l = s2 + (size_t)l * DMODEL;

        if (l == 0)
            modulate_kernel<<<SDIM, 256>>>(p_tokens, p_h, s1, modl, MODW, 0, 768);

        gemm_bf16<0><<<dim3(2304/128, SDIM/128, 1), 256, GEMM_SMEM>>>(
            p_hh, p_hl, p_whi + lb + OFF_QKV, p_wlo + lb + OFF_QKV,
            p_qkv, SDIM, 2304, 768, 768, nullptr, nullptr, nullptr);
        splitnorm_kernel<<<dim3(SDIM, NHEAD), 64>>>(sql, skl);
        flash_tc<<<dim3(SDIM/64, NHEAD), 128, FLASH_SMEM>>>();
        gemm_bf16<0><<<dim3(768/128, SDIM/128, 3), 256, GEMM_SMEM>>>(
            p_zh, p_zl, p_whi + lb + OFF_WO, p_wlo + lb + OFF_WO,
            p_u, SDIM, 768, 256, 768, nullptr, nullptr, nullptr);
        fusedCM<<<SDIM, 256>>>(p_u, modl + 1536, MODW, s2l, modl, MODW, 2304, 3072, nullptr);
        gemm_bf16<0><<<dim3(3072/128, SDIM/128, 1), 256, GEMM_SMEM>>>(
            p_hh, p_hl, p_whi + lb + OFF_UP, p_wlo + lb + OFF_UP,
            p_u, SDIM, 3072, 768, 768, nullptr, nullptr, nullptr);
        gemm_bf16<2><<<dim3(3072/128, SDIM/128, 1), 256, GEMM_SMEM>>>(
            p_hh, p_hl, p_whi + lb + OFF_GATE, p_wlo + lb + OFF_GATE,
            nullptr, SDIM, 3072, 768, 768, p_u, p_acth, p_actl);
        gemm_bf16<0><<<dim3(768/128, SDIM/128, 3), 256, GEMM_SMEM>>>(
            p_acth, p_actl, p_whi + lb + OFF_DOWN, p_wlo + lb + OFF_DOWN,
            p_u, SDIM, 768, 1024, 3072, nullptr, nullptr, nullptr);
        if (l + 1 < NLAYER) {
            float* modn = p_mod + (size_t)(l+1) * TFRM * MODW;
            fusedCM<<<SDIM, 256>>>(p_u, modl + 3840, MODW, s1 + (size_t)(l+1)*DMODEL,
                                   modn, MODW, 0, 768, nullptr);
        } else {
            fusedCM<<<SDIM, 256>>>(p_u, modl + 3840, MODW, s_final,
                                   p_mf, 2*DMODEL, 0, 768, p_h);
        }
    }

    outproj_kernel<<<SDIM, 64>>>(Wout, bout, out);
}